// round 13
// baseline (speedup 1.0000x reference)
#include <cuda_runtime.h>
#include <cuda_fp16.h>
#include <cstdint>
#include <math.h>

#define DD 128
#define N0CAP 100000
#define N1CAP 50000
#define N2CAP 50000
#define E1CAP 1600000
#define E2CAP 1600000
#define E12CAP 800000

// ---------------- scratch ----------------
__device__ __half g_xnodeh[N0CAP * DD];
__device__ __half g_net1h [N1CAP * DD];
__device__ __half g_net2h [N2CAP * DD];
__device__ __half g_net2bh[N2CAP * DD];
__device__ __half g_s1h[N0CAP * DD];
__device__ __half g_s2h[N0CAP * DD];
__device__ __half g_s12h[N0CAP * DD];
__device__ __half g_Wh[3 * DD * DD];
__device__ float  g_s1 [N0CAP * DD];
__device__ float  g_s2 [N0CAP * DD];
__device__ float  g_s12[N0CAP * DD];

#define RP1   0
#define RP2   (RP1 + N1CAP + 1)
#define RPB1  (RP2 + N2CAP + 1)
#define RPC   (RPB1 + N0CAP + 1)
#define RPB2  (RPC + N2CAP + 1)
#define RPTOT (RPB2 + N0CAP + 1)
__device__ int g_rowptr[RPTOT];
__device__ int g_cursor[RPTOT];   // doubles as histogram

__device__ int2 g_p1gw [E1CAP];   // (gather idx, weight bits)
__device__ int2 g_p2gw [E2CAP];
__device__ int2 g_pb2gw[E2CAP];
__device__ int  g_pb1g [E1CAP];
__device__ int  g_pcg  [E12CAP];

// ---------------- fp32 -> fp16 conversion ----------------
__global__ void k_f2h(const float* __restrict__ src, __half* __restrict__ dst, int n4)
{
    int t = blockIdx.x * blockDim.x + threadIdx.x;
    if (t >= n4) return;
    float4 v = __ldg((const float4*)src + t);
    __half2 h0 = __floats2half2_rn(v.x, v.y);
    __half2 h1 = __floats2half2_rn(v.z, v.w);
    ((uint2*)dst)[t] = make_uint2(*(unsigned*)&h0, *(unsigned*)&h1);
}

// 3 weight matrices in one launch (each DD*DD floats)
__global__ void k_f2h3(const float* __restrict__ w1, const float* __restrict__ w2,
                       const float* __restrict__ w3, __half* __restrict__ dst)
{
    int t = blockIdx.x * blockDim.x + threadIdx.x;   // grid covers 3*DD*DD/4
    const int per = DD * DD / 4;
    if (t >= 3 * per) return;
    int m = t / per, i = t - m * per;
    const float* src = (m == 0) ? w1 : (m == 1) ? w2 : w3;
    float4 v = __ldg((const float4*)src + i);
    __half2 h0 = __floats2half2_rn(v.x, v.y);
    __half2 h1 = __floats2half2_rn(v.z, v.w);
    ((uint2*)dst)[t] = make_uint2(*(unsigned*)&h0, *(unsigned*)&h1);
}

// ---------------- histogram ----------------
__global__ void k_hist(const int* __restrict__ idx, int* __restrict__ hist, int E)
{
    int e = blockIdx.x * blockDim.x + threadIdx.x;
    if (e < E) atomicAdd(hist + __ldg(idx + e), 1);
}

// ---------------- fused exclusive scan over 5 segments ----------------
struct Seg5 { int off[5]; int n[5]; };
__global__ void k_scan5(int* __restrict__ rowptr_base, int* __restrict__ cur_base, Seg5 segs)
{
    __shared__ int wsum[32];
    int off = segs.off[blockIdx.x];
    int N   = segs.n[blockIdx.x];
    int* hist = cur_base + off;
    int* rp   = rowptr_base + off;

    int tid = threadIdx.x;                 // blockDim = 1024
    int per = (N + 1023) >> 10;
    int lo = tid * per; if (lo > N) lo = N;
    int hi = lo + per;  if (hi > N) hi = N;

    int sum = 0;
    for (int i = lo; i < hi; i++) sum += hist[i];

    int lane = tid & 31, wid = tid >> 5;
    int v = sum;
#pragma unroll
    for (int o = 1; o < 32; o <<= 1) {
        int t = __shfl_up_sync(0xffffffffu, v, o);
        if (lane >= o) v += t;
    }
    if (lane == 31) wsum[wid] = v;
    __syncthreads();
    if (wid == 0) {
        int s = wsum[lane];
#pragma unroll
        for (int o = 1; o < 32; o <<= 1) {
            int t = __shfl_up_sync(0xffffffffu, s, o);
            if (lane >= o) s += t;
        }
        wsum[lane] = s;
    }
    __syncthreads();
    int excl = (v - sum) + (wid ? wsum[wid - 1] : 0);

    int run = excl;
    for (int i = lo; i < hi; i++) {
        int c = hist[i];
        rp[i] = run;
        hist[i] = run;
        run += c;
    }
    if (tid == 1023) rp[N] = excl + sum;
}

// ---------------- binning ----------------
__global__ void k_bin_w(const int*   __restrict__ sc_idx,
                        const int*   __restrict__ g_idx,
                        const float* __restrict__ ew,
                        int*  __restrict__ cursor,
                        int2* __restrict__ pgw,
                        int E)
{
    int e = blockIdx.x * blockDim.x + threadIdx.x;
    if (e >= E) return;
    int b = __ldg(sc_idx + e);
    int p = atomicAdd(cursor + b, 1);
    pgw[p] = make_int2(__ldg(g_idx + e), __float_as_int(__ldg(ew + e)));
}

__global__ void k_bin_u(const int* __restrict__ sc_idx,
                        const int* __restrict__ g_idx,
                        int* __restrict__ cursor,
                        int* __restrict__ pg,
                        int E)
{
    int e = blockIdx.x * blockDim.x + threadIdx.x;
    if (e >= E) return;
    int b = __ldg(sc_idx + e);
    int p = atomicAdd(cursor + b, 1);
    pg[p] = __ldg(g_idx + e);
}

// ======== gather A: fp16 src, weighted(packed), out = half((mean + xb)*0.5), MLP=8 ========
__global__ void k_gather_msg_h16(const __half* __restrict__ feath,
                                 const int2*   __restrict__ pgw,
                                 const int*    __restrict__ rp,
                                 const float*  __restrict__ xb,
                                 __half* __restrict__ outh,
                                 int N)
{
    int t = blockIdx.x * blockDim.x + threadIdx.x;
    int n = t >> 5, lane = t & 31;
    if (n >= N) return;
    int start = __ldg(rp + n), end = __ldg(rp + n + 1);
    const uint2* fb = (const uint2*)feath;

    float4 acc = make_float4(0.f, 0.f, 0.f, 0.f);
    int j = start;
    for (; j + 8 <= end; j += 8) {
        int2 e[8]; uint2 u[8];
#pragma unroll
        for (int q = 0; q < 8; q++) e[q] = __ldg(pgw + j + q);
#pragma unroll
        for (int q = 0; q < 8; q++) u[q] = __ldg(fb + (size_t)e[q].x * 32 + lane);
#pragma unroll
        for (int q = 0; q < 8; q++) {
            float w = __int_as_float(e[q].y);
            float2 f0 = __half22float2(*(__half2*)&u[q].x);
            float2 f1 = __half22float2(*(__half2*)&u[q].y);
            acc.x += f0.x * w; acc.y += f0.y * w;
            acc.z += f1.x * w; acc.w += f1.y * w;
        }
    }
    for (; j < end; j++) {
        int2 e = __ldg(pgw + j);
        float w = __int_as_float(e.y);
        uint2 u = __ldg(fb + (size_t)e.x * 32 + lane);
        float2 f0 = __half22float2(*(__half2*)&u.x);
        float2 f1 = __half22float2(*(__half2*)&u.y);
        acc.x += f0.x * w; acc.y += f0.y * w; acc.z += f1.x * w; acc.w += f1.y * w;
    }
    int deg = end - start;
    float inv = 1.0f / (deg > 1 ? (float)deg : 1.0f);
    float4 x = __ldg((const float4*)(xb + (size_t)n * DD) + lane);
    float4 r;
    r.x = (acc.x * inv + x.x) * 0.5f;
    r.y = (acc.y * inv + x.y) * 0.5f;
    r.z = (acc.z * inv + x.z) * 0.5f;
    r.w = (acc.w * inv + x.w) * 0.5f;
    __half2 h0 = __floats2half2_rn(r.x, r.y);
    __half2 h1 = __floats2half2_rn(r.z, r.w);
    ((uint2*)outh)[(size_t)n * 32 + lane] = make_uint2(*(unsigned*)&h0, *(unsigned*)&h1);
}

// ======== gather B: fp16 src, unweighted, out = half(mean), MLP=8 ========
__global__ void k_gather_s_h(const __half* __restrict__ feath,
                             const int*    __restrict__ pg,
                             const int*    __restrict__ rp,
                             __half* __restrict__ outh,
                             int N)
{
    int t = blockIdx.x * blockDim.x + threadIdx.x;
    int n = t >> 5, lane = t & 31;
    if (n >= N) return;
    int start = __ldg(rp + n), end = __ldg(rp + n + 1);
    const uint2* fb = (const uint2*)feath;

    float4 acc = make_float4(0.f, 0.f, 0.f, 0.f);
    int j = start;
    for (; j + 8 <= end; j += 8) {
        int g[8]; uint2 u[8];
#pragma unroll
        for (int q = 0; q < 8; q++) g[q] = __ldg(pg + j + q);
#pragma unroll
        for (int q = 0; q < 8; q++) u[q] = __ldg(fb + (size_t)g[q] * 32 + lane);
#pragma unroll
        for (int q = 0; q < 8; q++) {
            float2 f0 = __half22float2(*(__half2*)&u[q].x);
            float2 f1 = __half22float2(*(__half2*)&u[q].y);
            acc.x += f0.x; acc.y += f0.y; acc.z += f1.x; acc.w += f1.y;
        }
    }
    for (; j < end; j++) {
        int g = __ldg(pg + j);
        uint2 u = __ldg(fb + (size_t)g * 32 + lane);
        float2 f0 = __half22float2(*(__half2*)&u.x);
        float2 f1 = __half22float2(*(__half2*)&u.y);
        acc.x += f0.x; acc.y += f0.y; acc.z += f1.x; acc.w += f1.y;
    }
    int deg = end - start;
    float inv = 1.0f / (deg > 1 ? (float)deg : 1.0f);
    __half2 h0 = __floats2half2_rn(acc.x * inv, acc.y * inv);
    __half2 h1 = __floats2half2_rn(acc.z * inv, acc.w * inv);
    ((uint2*)outh)[(size_t)n * 32 + lane] = make_uint2(*(unsigned*)&h0, *(unsigned*)&h1);
}

// ======== gather C: fp16 src, unweighted, out = half((mean + xb)*0.5), MLP=8 ========
__global__ void k_gather_msg_hh(const __half* __restrict__ feath,
                                const int*    __restrict__ pg,
                                const int*    __restrict__ rp,
                                const float*  __restrict__ xb,
                                __half* __restrict__ outh,
                                int N)
{
    int t = blockIdx.x * blockDim.x + threadIdx.x;
    int n = t >> 5, lane = t & 31;
    if (n >= N) return;
    int start = __ldg(rp + n), end = __ldg(rp + n + 1);
    const uint2* fb = (const uint2*)feath;

    float4 acc = make_float4(0.f, 0.f, 0.f, 0.f);
    int j = start;
    for (; j + 8 <= end; j += 8) {
        int g[8]; uint2 u[8];
#pragma unroll
        for (int q = 0; q < 8; q++) g[q] = __ldg(pg + j + q);
#pragma unroll
        for (int q = 0; q < 8; q++) u[q] = __ldg(fb + (size_t)g[q] * 32 + lane);
#pragma unroll
        for (int q = 0; q < 8; q++) {
            float2 f0 = __half22float2(*(__half2*)&u[q].x);
            float2 f1 = __half22float2(*(__half2*)&u[q].y);
            acc.x += f0.x; acc.y += f0.y; acc.z += f1.x; acc.w += f1.y;
        }
    }
    for (; j < end; j++) {
        int g = __ldg(pg + j);
        uint2 u = __ldg(fb + (size_t)g * 32 + lane);
        float2 f0 = __half22float2(*(__half2*)&u.x);
        float2 f1 = __half22float2(*(__half2*)&u.y);
        acc.x += f0.x; acc.y += f0.y; acc.z += f1.x; acc.w += f1.y;
    }
    int deg = end - start;
    float inv = 1.0f / (deg > 1 ? (float)deg : 1.0f);
    float4 x = __ldg((const float4*)(xb + (size_t)n * DD) + lane);
    float4 r;
    r.x = (acc.x * inv + x.x) * 0.5f;
    r.y = (acc.y * inv + x.y) * 0.5f;
    r.z = (acc.z * inv + x.z) * 0.5f;
    r.w = (acc.w * inv + x.w) * 0.5f;
    __half2 h0 = __floats2half2_rn(r.x, r.y);
    __half2 h1 = __floats2half2_rn(r.z, r.w);
    ((uint2*)outh)[(size_t)n * 32 + lane] = make_uint2(*(unsigned*)&h0, *(unsigned*)&h1);
}

// ======== dual gather: fp16 srcs, packed weight (b only), half outs, 4-edge unroll ========
__global__ void k_gather_dual_h(const __half* __restrict__ feat_a,
                                const __half* __restrict__ feat_b,
                                const int2*   __restrict__ pgw,
                                const int*    __restrict__ rp,
                                __half* __restrict__ out_a,
                                __half* __restrict__ out_b,
                                int N)
{
    int t = blockIdx.x * blockDim.x + threadIdx.x;
    int n = t >> 5, lane = t & 31;
    if (n >= N) return;
    int start = __ldg(rp + n), end = __ldg(rp + n + 1);
    const uint2* fa = (const uint2*)feat_a;
    const uint2* fbp = (const uint2*)feat_b;

    float4 aa = make_float4(0.f, 0.f, 0.f, 0.f);
    float4 ab = make_float4(0.f, 0.f, 0.f, 0.f);
    int j = start;
    for (; j + 4 <= end; j += 4) {
        int2 e[4]; uint2 ua[4], ub[4];
#pragma unroll
        for (int q = 0; q < 4; q++) e[q] = __ldg(pgw + j + q);
#pragma unroll
        for (int q = 0; q < 4; q++) {
            ua[q] = __ldg(fa  + (size_t)e[q].x * 32 + lane);
            ub[q] = __ldg(fbp + (size_t)e[q].x * 32 + lane);
        }
#pragma unroll
        for (int q = 0; q < 4; q++) {
            float w = __int_as_float(e[q].y);
            float2 f0 = __half22float2(*(__half2*)&ua[q].x);
            float2 f1 = __half22float2(*(__half2*)&ua[q].y);
            aa.x += f0.x; aa.y += f0.y; aa.z += f1.x; aa.w += f1.y;
            float2 h0 = __half22float2(*(__half2*)&ub[q].x);
            float2 h1 = __half22float2(*(__half2*)&ub[q].y);
            ab.x += h0.x * w; ab.y += h0.y * w; ab.z += h1.x * w; ab.w += h1.y * w;
        }
    }
    for (; j < end; j++) {
        int2 e = __ldg(pgw + j);
        float w = __int_as_float(e.y);
        uint2 a = __ldg(fa  + (size_t)e.x * 32 + lane);
        uint2 b = __ldg(fbp + (size_t)e.x * 32 + lane);
        float2 f0 = __half22float2(*(__half2*)&a.x);
        float2 f1 = __half22float2(*(__half2*)&a.y);
        aa.x += f0.x; aa.y += f0.y; aa.z += f1.x; aa.w += f1.y;
        float2 h0 = __half22float2(*(__half2*)&b.x);
        float2 h1 = __half22float2(*(__half2*)&b.y);
        ab.x += h0.x * w; ab.y += h0.y * w; ab.z += h1.x * w; ab.w += h1.y * w;
    }
    int deg = end - start;
    float inv = 1.0f / (deg > 1 ? (float)deg : 1.0f);
    __half2 ha0 = __floats2half2_rn(aa.x * inv, aa.y * inv);
    __half2 ha1 = __floats2half2_rn(aa.z * inv, aa.w * inv);
    __half2 hb0 = __floats2half2_rn(ab.x * inv, ab.y * inv);
    __half2 hb1 = __floats2half2_rn(ab.z * inv, ab.w * inv);
    ((uint2*)out_a)[(size_t)n * 32 + lane] = make_uint2(*(unsigned*)&ha0, *(unsigned*)&ha1);
    ((uint2*)out_b)[(size_t)n * 32 + lane] = make_uint2(*(unsigned*)&hb0, *(unsigned*)&hb1);
}

// ======== tensor-core GEMM: out_f32 = relu(xh @ Wh^T + b) ========
#define APITCH 136
#define MMA_SMEM (2 * 128 * APITCH * 2)

__device__ __forceinline__ unsigned smem_u32p(const void* p) {
    return (unsigned)__cvta_generic_to_shared(p);
}

__global__ void __launch_bounds__(256, 2)
k_gemm_mma(const __half* __restrict__ xh,
           const __half* __restrict__ Wh,     // [n][k] row-major
           const float* __restrict__ bias,
           float* __restrict__ out,
           int N)
{
    extern __shared__ __half smh[];
    __half* As = smh;                  // [128][APITCH]
    __half* Bs = smh + 128 * APITCH;   // [128][APITCH]
    int tid = threadIdx.x;
    int lane = tid & 31, wid = tid >> 5;
    int row0 = blockIdx.x * 128;

    for (int i = tid; i < 128 * 16; i += 256) {
        int r = i >> 4, c = i & 15;
        uint4 v = *((const uint4*)(Wh + r * DD) + c);
        *(uint4*)(Bs + r * APITCH + c * 8) = v;
    }
    for (int i = tid; i < 128 * 16; i += 256) {
        int r = i >> 4, c = i & 15;
        int row = row0 + r;
        uint4 v = make_uint4(0u, 0u, 0u, 0u);
        if (row < N) v = *((const uint4*)(xh + (size_t)row * DD) + c);
        *(uint4*)(As + r * APITCH + c * 8) = v;
    }
    __syncthreads();

    float d[16][4];
#pragma unroll
    for (int t = 0; t < 16; t++) { d[t][0] = d[t][1] = d[t][2] = d[t][3] = 0.f; }

    int wm = wid * 16;
    int qr = lane & 7, q = lane >> 3;

#pragma unroll
    for (int kk = 0; kk < 8; kk++) {
        int arow = wm + qr + (q & 1) * 8;
        int acol = kk * 16 + (q >> 1) * 8;
        unsigned a0, a1, a2, a3;
        {
            unsigned addr = smem_u32p(As + arow * APITCH + acol);
            asm volatile("ldmatrix.sync.aligned.m8n8.x4.shared.b16 {%0,%1,%2,%3}, [%4];"
                         : "=r"(a0), "=r"(a1), "=r"(a2), "=r"(a3) : "r"(addr));
        }
#pragma unroll
        for (int bt = 0; bt < 8; bt++) {
            int brow = bt * 16 + qr + (q >> 1) * 8;
            int bcol = kk * 16 + (q & 1) * 8;
            unsigned b0, b1, b2, b3;
            unsigned addr = smem_u32p(Bs + brow * APITCH + bcol);
            asm volatile("ldmatrix.sync.aligned.m8n8.x4.shared.b16 {%0,%1,%2,%3}, [%4];"
                         : "=r"(b0), "=r"(b1), "=r"(b2), "=r"(b3) : "r"(addr));
            float* dt0 = d[2 * bt];
            asm volatile("mma.sync.aligned.m16n8k16.row.col.f32.f16.f16.f32 "
                         "{%0,%1,%2,%3}, {%4,%5,%6,%7}, {%8,%9}, {%0,%1,%2,%3};"
                         : "+f"(dt0[0]), "+f"(dt0[1]), "+f"(dt0[2]), "+f"(dt0[3])
                         : "r"(a0), "r"(a1), "r"(a2), "r"(a3), "r"(b0), "r"(b1));
            float* dt1 = d[2 * bt + 1];
            asm volatile("mma.sync.aligned.m16n8k16.row.col.f32.f16.f16.f32 "
                         "{%0,%1,%2,%3}, {%4,%5,%6,%7}, {%8,%9}, {%0,%1,%2,%3};"
                         : "+f"(dt1[0]), "+f"(dt1[1]), "+f"(dt1[2]), "+f"(dt1[3])
                         : "r"(a0), "r"(a1), "r"(a2), "r"(a3), "r"(b2), "r"(b3));
        }
    }

    int r_lo = row0 + wm + (lane >> 2);
    int cbase = (lane & 3) * 2;
#pragma unroll
    for (int t = 0; t < 16; t++) {
        int col = t * 8 + cbase;
        float bb0 = __ldg(bias + col), bb1 = __ldg(bias + col + 1);
        if (r_lo < N) {
            float2 v = make_float2(fmaxf(d[t][0] + bb0, 0.f), fmaxf(d[t][1] + bb1, 0.f));
            *(float2*)(out + (size_t)r_lo * DD + col) = v;
        }
        if (r_lo + 8 < N) {
            float2 v = make_float2(fmaxf(d[t][2] + bb0, 0.f), fmaxf(d[t][3] + bb1, 0.f));
            *(float2*)(out + (size_t)(r_lo + 8) * DD + col) = v;
        }
    }
}

// ---------------- attention combine ----------------
__global__ void k_att(const float* __restrict__ y1,
                      const float* __restrict__ y2,
                      const float* __restrict__ y3,
                      const float* __restrict__ att,
                      float* __restrict__ out,
                      int N)
{
    int t = blockIdx.x * blockDim.x + threadIdx.x;
    int n = t >> 5, lane = t & 31;
    if (n >= N) return;
    size_t base = (size_t)n * DD;
    float4 v1 = __ldg((const float4*)(y1 + base) + lane);
    float4 v2 = __ldg((const float4*)(y2 + base) + lane);
    float4 v3 = __ldg((const float4*)(y3 + base) + lane);
    float4 a1 = __ldg((const float4*)att + lane);
    float4 a2 = __ldg((const float4*)att + 32 + lane);
    float4 a3 = __ldg((const float4*)att + 64 + lane);

    float s1 = v1.x * a1.x + v1.y * a1.y + v1.z * a1.z + v1.w * a1.w;
    float s2 = v2.x * a2.x + v2.y * a2.y + v2.z * a2.z + v2.w * a2.w;
    float s3 = v3.x * a3.x + v3.y * a3.y + v3.z * a3.z + v3.w * a3.w;
#pragma unroll
    for (int off = 16; off; off >>= 1) {
        s1 += __shfl_xor_sync(0xFFFFFFFFu, s1, off);
        s2 += __shfl_xor_sync(0xFFFFFFFFu, s2, off);
        s3 += __shfl_xor_sync(0xFFFFFFFFu, s3, off);
    }
    float m = fmaxf(s1, fmaxf(s2, s3));
    float e1 = __expf(s1 - m), e2 = __expf(s2 - m), e3 = __expf(s3 - m);
    float inv = 1.0f / (e1 + e2 + e3);
    float w1 = e1 * inv, w2 = e2 * inv, w3 = e3 * inv;

    float4 o;
    o.x = w1 * v1.x + w2 * v2.x + w3 * v3.x;
    o.y = w1 * v1.y + w2 * v2.y + w3 * v3.y;
    o.z = w1 * v1.z + w2 * v2.z + w3 * v3.z;
    o.w = w1 * v1.w + w2 * v2.w + w3 * v3.w;
    ((float4*)(out + base))[lane] = o;
}

// ---------------- launch ----------------
static inline int cdiv(long long a, int b) { return (int)((a + b - 1) / b); }

extern "C" void kernel_launch(void* const* d_in, const int* in_sizes, int n_in,
                              void* d_out, int out_size)
{
    const float* x_node   = (const float*)d_in[0];
    const float* x1       = (const float*)d_in[1];
    const float* x2       = (const float*)d_in[2];
    const int*   ei1_src  = (const int*)d_in[3];
    const int*   ei1_dst  = (const int*)d_in[4];
    const int*   ei2_src  = (const int*)d_in[5];
    const int*   ei2_dst  = (const int*)d_in[6];
    const int*   ei12_src = (const int*)d_in[7];
    const int*   ei12_dst = (const int*)d_in[8];
    const float* ew1      = (const float*)d_in[9];
    const float* ew2      = (const float*)d_in[10];
    const float* W1       = (const float*)d_in[11];
    const float* b1       = (const float*)d_in[12];
    const float* W2       = (const float*)d_in[13];
    const float* b2       = (const float*)d_in[14];
    const float* W12      = (const float*)d_in[15];
    const float* b12      = (const float*)d_in[16];
    const float* att      = (const float*)d_in[17];
    float* out = (float*)d_out;

    int n0  = in_sizes[0] / DD;
    int n1  = in_sizes[1] / DD;
    int n2  = in_sizes[2] / DD;
    int e1  = in_sizes[3];
    int e2  = in_sizes[5];
    int e12 = in_sizes[7];

    __half *xnodeh, *net1h, *net2h, *net2bh, *s1h, *s2h, *s12h, *Wh;
    float *s1, *s2, *s12;
    int *rowptr, *cursor, *pb1g, *pcg;
    int2 *p1gw, *p2gw, *pb2gw;
    cudaGetSymbolAddress((void**)&xnodeh, g_xnodeh);
    cudaGetSymbolAddress((void**)&net1h,  g_net1h);
    cudaGetSymbolAddress((void**)&net2h,  g_net2h);
    cudaGetSymbolAddress((void**)&net2bh, g_net2bh);
    cudaGetSymbolAddress((void**)&s1h,  g_s1h);
    cudaGetSymbolAddress((void**)&s2h,  g_s2h);
    cudaGetSymbolAddress((void**)&s12h, g_s12h);
    cudaGetSymbolAddress((void**)&Wh,   g_Wh);
    cudaGetSymbolAddress((void**)&s1,  g_s1);
    cudaGetSymbolAddress((void**)&s2,  g_s2);
    cudaGetSymbolAddress((void**)&s12, g_s12);
    cudaGetSymbolAddress((void**)&rowptr, g_rowptr);
    cudaGetSymbolAddress((void**)&cursor, g_cursor);
    cudaGetSymbolAddress((void**)&p1gw,  g_p1gw);
    cudaGetSymbolAddress((void**)&p2gw,  g_p2gw);
    cudaGetSymbolAddress((void**)&pb2gw, g_pb2gw);
    cudaGetSymbolAddress((void**)&pb1g,  g_pb1g);
    cudaGetSymbolAddress((void**)&pcg,   g_pcg);

    cudaFuncSetAttribute(k_gemm_mma, cudaFuncAttributeMaxDynamicSharedMemorySize, MMA_SMEM);

    cudaMemsetAsync(cursor, 0, (size_t)RPTOT * sizeof(int), 0);

    const int BT = 256;

    // --- conversions ---
    k_f2h<<<cdiv((long long)n0 * 32, BT), BT>>>(x_node, xnodeh, n0 * 32);
    k_f2h3<<<cdiv(3 * DD * DD / 4, BT), BT>>>(W1, W2, W12, Wh);

    // --- histograms ---
    k_hist<<<cdiv(e1, BT), BT>>>(ei1_dst,   cursor + RP1,  e1);
    k_hist<<<cdiv(e2, BT), BT>>>(ei2_dst,   cursor + RP2,  e2);
    k_hist<<<cdiv(e1, BT), BT>>>(ei1_src,   cursor + RPB1, e1);
    k_hist<<<cdiv(e12, BT), BT>>>(ei12_dst, cursor + RPC,  e12);
    k_hist<<<cdiv(e2, BT), BT>>>(ei2_src,   cursor + RPB2, e2);

    // --- fused scans ---
    Seg5 segs;
    segs.off[0] = RP1;  segs.n[0] = n1;
    segs.off[1] = RP2;  segs.n[1] = n2;
    segs.off[2] = RPB1; segs.n[2] = n0;
    segs.off[3] = RPC;  segs.n[3] = n2;
    segs.off[4] = RPB2; segs.n[4] = n0;
    k_scan5<<<5, 1024>>>(rowptr, cursor, segs);

    // --- binning ---
    k_bin_w<<<cdiv(e1, BT), BT>>>(ei1_dst,  ei1_src,  ew1, cursor + RP1,  p1gw,  e1);
    k_bin_w<<<cdiv(e2, BT), BT>>>(ei2_dst,  ei2_src,  ew2, cursor + RP2,  p2gw,  e2);
    k_bin_u<<<cdiv(e1, BT), BT>>>(ei1_src,  ei1_dst,  cursor + RPB1, pb1g, e1);
    k_bin_u<<<cdiv(e12, BT), BT>>>(ei12_dst, ei12_src, cursor + RPC,  pcg,  e12);
    k_bin_w<<<cdiv(e2, BT), BT>>>(ei2_src,  ei2_dst,  ew2, cursor + RPB2, pb2gw, e2);

    // --- gathers ---
    k_gather_msg_h16<<<cdiv((long long)n1 * 32, BT), BT>>>(xnodeh, p1gw, rowptr + RP1, x1, net1h, n1);
    k_gather_msg_h16<<<cdiv((long long)n2 * 32, BT), BT>>>(xnodeh, p2gw, rowptr + RP2, x2, net2h, n2);
    k_gather_s_h<<<cdiv((long long)n0 * 32, BT), BT>>>(net1h, pb1g, rowptr + RPB1, s1h, n0);
    k_gather_msg_hh<<<cdiv((long long)n2 * 32, BT), BT>>>(net1h, pcg, rowptr + RPC, x2, net2bh, n2);
    k_gather_dual_h<<<cdiv((long long)n0 * 32, BT), BT>>>(net2h, net2bh, pb2gw, rowptr + RPB2, s2h, s12h, n0);

    // --- tensor-core GEMM + bias + ReLU ---
    k_gemm_mma<<<cdiv(n0, 128), 256, MMA_SMEM>>>(s1h,  Wh,               b1,  s1,  n0);
    k_gemm_mma<<<cdiv(n0, 128), 256, MMA_SMEM>>>(s2h,  Wh + DD * DD,     b2,  s2,  n0);
    k_gemm_mma<<<cdiv(n0, 128), 256, MMA_SMEM>>>(s12h, Wh + 2 * DD * DD, b12, s12, n0);

    // --- attention combine ---
    k_att<<<cdiv((long long)n0 * 32, BT), BT>>>(s1, s2, s12, att, out, n0);
}

// round 14
// speedup vs baseline: 1.3987x; 1.3987x over previous
#include <cuda_runtime.h>
#include <cuda_fp16.h>
#include <cstdint>
#include <math.h>

#define DD 128
#define N0CAP 100000
#define N1CAP 50000
#define N2CAP 50000
#define E1CAP 1600000
#define E2CAP 1600000
#define E12CAP 800000

// ---------------- scratch ----------------
__device__ __half g_xnodeh[N0CAP * DD];
__device__ __half g_net1h [N1CAP * DD];
__device__ __half g_net2h [N2CAP * DD];
__device__ __half g_net2bh[N2CAP * DD];
__device__ __half g_s1h[N0CAP * DD];
__device__ __half g_s2h[N0CAP * DD];
__device__ __half g_s12h[N0CAP * DD];
__device__ __half g_Wh[3 * DD * DD];
__device__ float  g_s1 [N0CAP * DD];
__device__ float  g_s2 [N0CAP * DD];
__device__ float  g_s12[N0CAP * DD];

#define RP1   0
#define RP2   (RP1 + N1CAP + 1)
#define RPB1  (RP2 + N2CAP + 1)
#define RPC   (RPB1 + N0CAP + 1)
#define RPB2  (RPC + N2CAP + 1)
#define RPTOT (RPB2 + N0CAP + 1)
__device__ int g_rowptr[RPTOT];
__device__ int g_cursor[RPTOT];   // doubles as histogram

__device__ int2 g_p1gw [E1CAP];   // (gather idx, weight bits)
__device__ int2 g_p2gw [E2CAP];
__device__ int2 g_pb2gw[E2CAP];
__device__ int  g_pb1g [E1CAP];
__device__ int  g_pcg  [E12CAP];

// ---------------- fp32 -> fp16 conversion ----------------
__global__ void k_f2h(const float* __restrict__ src, __half* __restrict__ dst, int n4)
{
    int t = blockIdx.x * blockDim.x + threadIdx.x;
    if (t >= n4) return;
    float4 v = __ldg((const float4*)src + t);
    __half2 h0 = __floats2half2_rn(v.x, v.y);
    __half2 h1 = __floats2half2_rn(v.z, v.w);
    ((uint2*)dst)[t] = make_uint2(*(unsigned*)&h0, *(unsigned*)&h1);
}

// 3 weight matrices in one launch
__global__ void k_f2h3(const float* __restrict__ w1, const float* __restrict__ w2,
                       const float* __restrict__ w3, __half* __restrict__ dst)
{
    int t = blockIdx.x * blockDim.x + threadIdx.x;
    const int per = DD * DD / 4;
    if (t >= 3 * per) return;
    int m = t / per, i = t - m * per;
    const float* src = (m == 0) ? w1 : (m == 1) ? w2 : w3;
    float4 v = __ldg((const float4*)src + i);
    __half2 h0 = __floats2half2_rn(v.x, v.y);
    __half2 h1 = __floats2half2_rn(v.z, v.w);
    ((uint2*)dst)[t] = make_uint2(*(unsigned*)&h0, *(unsigned*)&h1);
}

// ---------------- histogram ----------------
__global__ void k_hist(const int* __restrict__ idx, int* __restrict__ hist, int E)
{
    int e = blockIdx.x * blockDim.x + threadIdx.x;
    if (e < E) atomicAdd(hist + __ldg(idx + e), 1);
}

// ---------------- fused exclusive scan over 5 segments ----------------
struct Seg5 { int off[5]; int n[5]; };
__global__ void k_scan5(int* __restrict__ rowptr_base, int* __restrict__ cur_base, Seg5 segs)
{
    __shared__ int wsum[32];
    int off = segs.off[blockIdx.x];
    int N   = segs.n[blockIdx.x];
    int* hist = cur_base + off;
    int* rp   = rowptr_base + off;

    int tid = threadIdx.x;                 // blockDim = 1024
    int per = (N + 1023) >> 10;
    int lo = tid * per; if (lo > N) lo = N;
    int hi = lo + per;  if (hi > N) hi = N;

    int sum = 0;
    for (int i = lo; i < hi; i++) sum += hist[i];

    int lane = tid & 31, wid = tid >> 5;
    int v = sum;
#pragma unroll
    for (int o = 1; o < 32; o <<= 1) {
        int t = __shfl_up_sync(0xffffffffu, v, o);
        if (lane >= o) v += t;
    }
    if (lane == 31) wsum[wid] = v;
    __syncthreads();
    if (wid == 0) {
        int s = wsum[lane];
#pragma unroll
        for (int o = 1; o < 32; o <<= 1) {
            int t = __shfl_up_sync(0xffffffffu, s, o);
            if (lane >= o) s += t;
        }
        wsum[lane] = s;
    }
    __syncthreads();
    int excl = (v - sum) + (wid ? wsum[wid - 1] : 0);

    int run = excl;
    for (int i = lo; i < hi; i++) {
        int c = hist[i];
        rp[i] = run;
        hist[i] = run;
        run += c;
    }
    if (tid == 1023) rp[N] = excl + sum;
}

// ---------------- binning ----------------
__global__ void k_bin_w(const int*   __restrict__ sc_idx,
                        const int*   __restrict__ g_idx,
                        const float* __restrict__ ew,
                        int*  __restrict__ cursor,
                        int2* __restrict__ pgw,
                        int E)
{
    int e = blockIdx.x * blockDim.x + threadIdx.x;
    if (e >= E) return;
    int b = __ldg(sc_idx + e);
    int p = atomicAdd(cursor + b, 1);
    pgw[p] = make_int2(__ldg(g_idx + e), __float_as_int(__ldg(ew + e)));
}

__global__ void k_bin_u(const int* __restrict__ sc_idx,
                        const int* __restrict__ g_idx,
                        int* __restrict__ cursor,
                        int* __restrict__ pg,
                        int E)
{
    int e = blockIdx.x * blockDim.x + threadIdx.x;
    if (e >= E) return;
    int b = __ldg(sc_idx + e);
    int p = atomicAdd(cursor + b, 1);
    pg[p] = __ldg(g_idx + e);
}

// ======== gather A: fp16 src, weighted(packed), out = half((mean + xb)*0.5) [R11/MLP4] ========
__global__ void k_gather_msg_h16(const __half* __restrict__ feath,
                                 const int2*   __restrict__ pgw,
                                 const int*    __restrict__ rp,
                                 const float*  __restrict__ xb,
                                 __half* __restrict__ outh,
                                 int N)
{
    int t = blockIdx.x * blockDim.x + threadIdx.x;
    int n = t >> 5, lane = t & 31;
    if (n >= N) return;
    int start = __ldg(rp + n), end = __ldg(rp + n + 1);
    const uint2* fb = (const uint2*)feath;

    float4 acc = make_float4(0.f, 0.f, 0.f, 0.f);
    int j = start;
    for (; j + 4 <= end; j += 4) {
        int2 e0 = __ldg(pgw + j),     e1 = __ldg(pgw + j + 1);
        int2 e2 = __ldg(pgw + j + 2), e3 = __ldg(pgw + j + 3);
        uint2 u0 = __ldg(fb + (size_t)e0.x * 32 + lane);
        uint2 u1 = __ldg(fb + (size_t)e1.x * 32 + lane);
        uint2 u2 = __ldg(fb + (size_t)e2.x * 32 + lane);
        uint2 u3 = __ldg(fb + (size_t)e3.x * 32 + lane);
        float w0 = __int_as_float(e0.y), w1 = __int_as_float(e1.y);
        float w2 = __int_as_float(e2.y), w3 = __int_as_float(e3.y);
#pragma unroll
        for (int q = 0; q < 4; q++) {
            uint2 u = (q == 0) ? u0 : (q == 1) ? u1 : (q == 2) ? u2 : u3;
            float w = (q == 0) ? w0 : (q == 1) ? w1 : (q == 2) ? w2 : w3;
            float2 f0 = __half22float2(*(__half2*)&u.x);
            float2 f1 = __half22float2(*(__half2*)&u.y);
            acc.x += f0.x * w; acc.y += f0.y * w;
            acc.z += f1.x * w; acc.w += f1.y * w;
        }
    }
    for (; j < end; j++) {
        int2 e = __ldg(pgw + j);
        float w = __int_as_float(e.y);
        uint2 u = __ldg(fb + (size_t)e.x * 32 + lane);
        float2 f0 = __half22float2(*(__half2*)&u.x);
        float2 f1 = __half22float2(*(__half2*)&u.y);
        acc.x += f0.x * w; acc.y += f0.y * w; acc.z += f1.x * w; acc.w += f1.y * w;
    }
    int deg = end - start;
    float inv = 1.0f / (deg > 1 ? (float)deg : 1.0f);
    float4 x = __ldg((const float4*)(xb + (size_t)n * DD) + lane);
    float4 r;
    r.x = (acc.x * inv + x.x) * 0.5f;
    r.y = (acc.y * inv + x.y) * 0.5f;
    r.z = (acc.z * inv + x.z) * 0.5f;
    r.w = (acc.w * inv + x.w) * 0.5f;
    __half2 h0 = __floats2half2_rn(r.x, r.y);
    __half2 h1 = __floats2half2_rn(r.z, r.w);
    ((uint2*)outh)[(size_t)n * 32 + lane] = make_uint2(*(unsigned*)&h0, *(unsigned*)&h1);
}

// ======== gather B: fp16 src, unweighted, out = half(mean) [R11/MLP4] ========
__global__ void k_gather_s_h(const __half* __restrict__ feath,
                             const int*    __restrict__ pg,
                             const int*    __restrict__ rp,
                             __half* __restrict__ outh,
                             int N)
{
    int t = blockIdx.x * blockDim.x + threadIdx.x;
    int n = t >> 5, lane = t & 31;
    if (n >= N) return;
    int start = __ldg(rp + n), end = __ldg(rp + n + 1);
    const uint2* fb = (const uint2*)feath;

    float4 acc = make_float4(0.f, 0.f, 0.f, 0.f);
    int j = start;
    for (; j + 4 <= end; j += 4) {
        int g0 = __ldg(pg + j), g1 = __ldg(pg + j + 1);
        int g2 = __ldg(pg + j + 2), g3 = __ldg(pg + j + 3);
        uint2 u0 = __ldg(fb + (size_t)g0 * 32 + lane);
        uint2 u1 = __ldg(fb + (size_t)g1 * 32 + lane);
        uint2 u2 = __ldg(fb + (size_t)g2 * 32 + lane);
        uint2 u3 = __ldg(fb + (size_t)g3 * 32 + lane);
#pragma unroll
        for (int q = 0; q < 4; q++) {
            uint2 u = (q == 0) ? u0 : (q == 1) ? u1 : (q == 2) ? u2 : u3;
            float2 f0 = __half22float2(*(__half2*)&u.x);
            float2 f1 = __half22float2(*(__half2*)&u.y);
            acc.x += f0.x; acc.y += f0.y; acc.z += f1.x; acc.w += f1.y;
        }
    }
    for (; j < end; j++) {
        int g = __ldg(pg + j);
        uint2 u = __ldg(fb + (size_t)g * 32 + lane);
        float2 f0 = __half22float2(*(__half2*)&u.x);
        float2 f1 = __half22float2(*(__half2*)&u.y);
        acc.x += f0.x; acc.y += f0.y; acc.z += f1.x; acc.w += f1.y;
    }
    int deg = end - start;
    float inv = 1.0f / (deg > 1 ? (float)deg : 1.0f);
    __half2 h0 = __floats2half2_rn(acc.x * inv, acc.y * inv);
    __half2 h1 = __floats2half2_rn(acc.z * inv, acc.w * inv);
    ((uint2*)outh)[(size_t)n * 32 + lane] = make_uint2(*(unsigned*)&h0, *(unsigned*)&h1);
}

// ======== gather C: fp16 src, unweighted, out = half((mean + xb)*0.5) [R11/MLP4] ========
__global__ void k_gather_msg_hh(const __half* __restrict__ feath,
                                const int*    __restrict__ pg,
                                const int*    __restrict__ rp,
                                const float*  __restrict__ xb,
                                __half* __restrict__ outh,
                                int N)
{
    int t = blockIdx.x * blockDim.x + threadIdx.x;
    int n = t >> 5, lane = t & 31;
    if (n >= N) return;
    int start = __ldg(rp + n), end = __ldg(rp + n + 1);
    const uint2* fb = (const uint2*)feath;

    float4 acc = make_float4(0.f, 0.f, 0.f, 0.f);
    int j = start;
    for (; j + 4 <= end; j += 4) {
        int g0 = __ldg(pg + j), g1 = __ldg(pg + j + 1);
        int g2 = __ldg(pg + j + 2), g3 = __ldg(pg + j + 3);
        uint2 u0 = __ldg(fb + (size_t)g0 * 32 + lane);
        uint2 u1 = __ldg(fb + (size_t)g1 * 32 + lane);
        uint2 u2 = __ldg(fb + (size_t)g2 * 32 + lane);
        uint2 u3 = __ldg(fb + (size_t)g3 * 32 + lane);
#pragma unroll
        for (int q = 0; q < 4; q++) {
            uint2 u = (q == 0) ? u0 : (q == 1) ? u1 : (q == 2) ? u2 : u3;
            float2 f0 = __half22float2(*(__half2*)&u.x);
            float2 f1 = __half22float2(*(__half2*)&u.y);
            acc.x += f0.x; acc.y += f0.y; acc.z += f1.x; acc.w += f1.y;
        }
    }
    for (; j < end; j++) {
        int g = __ldg(pg + j);
        uint2 u = __ldg(fb + (size_t)g * 32 + lane);
        float2 f0 = __half22float2(*(__half2*)&u.x);
        float2 f1 = __half22float2(*(__half2*)&u.y);
        acc.x += f0.x; acc.y += f0.y; acc.z += f1.x; acc.w += f1.y;
    }
    int deg = end - start;
    float inv = 1.0f / (deg > 1 ? (float)deg : 1.0f);
    float4 x = __ldg((const float4*)(xb + (size_t)n * DD) + lane);
    float4 r;
    r.x = (acc.x * inv + x.x) * 0.5f;
    r.y = (acc.y * inv + x.y) * 0.5f;
    r.z = (acc.z * inv + x.z) * 0.5f;
    r.w = (acc.w * inv + x.w) * 0.5f;
    __half2 h0 = __floats2half2_rn(r.x, r.y);
    __half2 h1 = __floats2half2_rn(r.z, r.w);
    ((uint2*)outh)[(size_t)n * 32 + lane] = make_uint2(*(unsigned*)&h0, *(unsigned*)&h1);
}

// ======== dual gather: fp16 srcs, packed weight (b only), half outs [R11/2-edge] ========
__global__ void k_gather_dual_h(const __half* __restrict__ feat_a,
                                const __half* __restrict__ feat_b,
                                const int2*   __restrict__ pgw,
                                const int*    __restrict__ rp,
                                __half* __restrict__ out_a,
                                __half* __restrict__ out_b,
                                int N)
{
    int t = blockIdx.x * blockDim.x + threadIdx.x;
    int n = t >> 5, lane = t & 31;
    if (n >= N) return;
    int start = __ldg(rp + n), end = __ldg(rp + n + 1);
    const uint2* fa = (const uint2*)feat_a;
    const uint2* fbp = (const uint2*)feat_b;

    float4 aa = make_float4(0.f, 0.f, 0.f, 0.f);
    float4 ab = make_float4(0.f, 0.f, 0.f, 0.f);
    int j = start;
    for (; j + 2 <= end; j += 2) {
        int2 e0 = __ldg(pgw + j), e1 = __ldg(pgw + j + 1);
        uint2 a0 = __ldg(fa  + (size_t)e0.x * 32 + lane);
        uint2 b0 = __ldg(fbp + (size_t)e0.x * 32 + lane);
        uint2 a1 = __ldg(fa  + (size_t)e1.x * 32 + lane);
        uint2 b1 = __ldg(fbp + (size_t)e1.x * 32 + lane);
        float w0 = __int_as_float(e0.y), w1 = __int_as_float(e1.y);
        {
            float2 f0 = __half22float2(*(__half2*)&a0.x);
            float2 f1 = __half22float2(*(__half2*)&a0.y);
            float2 g0 = __half22float2(*(__half2*)&a1.x);
            float2 g1 = __half22float2(*(__half2*)&a1.y);
            aa.x += f0.x + g0.x; aa.y += f0.y + g0.y;
            aa.z += f1.x + g1.x; aa.w += f1.y + g1.y;
        }
        {
            float2 f0 = __half22float2(*(__half2*)&b0.x);
            float2 f1 = __half22float2(*(__half2*)&b0.y);
            float2 g0 = __half22float2(*(__half2*)&b1.x);
            float2 g1 = __half22float2(*(__half2*)&b1.y);
            ab.x += f0.x * w0 + g0.x * w1; ab.y += f0.y * w0 + g0.y * w1;
            ab.z += f1.x * w0 + g1.x * w1; ab.w += f1.y * w0 + g1.y * w1;
        }
    }
    for (; j < end; j++) {
        int2 e = __ldg(pgw + j);
        float w = __int_as_float(e.y);
        uint2 a = __ldg(fa  + (size_t)e.x * 32 + lane);
        uint2 b = __ldg(fbp + (size_t)e.x * 32 + lane);
        float2 f0 = __half22float2(*(__half2*)&a.x);
        float2 f1 = __half22float2(*(__half2*)&a.y);
        aa.x += f0.x; aa.y += f0.y; aa.z += f1.x; aa.w += f1.y;
        float2 h0 = __half22float2(*(__half2*)&b.x);
        float2 h1 = __half22float2(*(__half2*)&b.y);
        ab.x += h0.x * w; ab.y += h0.y * w; ab.z += h1.x * w; ab.w += h1.y * w;
    }
    int deg = end - start;
    float inv = 1.0f / (deg > 1 ? (float)deg : 1.0f);
    __half2 ha0 = __floats2half2_rn(aa.x * inv, aa.y * inv);
    __half2 ha1 = __floats2half2_rn(aa.z * inv, aa.w * inv);
    __half2 hb0 = __floats2half2_rn(ab.x * inv, ab.y * inv);
    __half2 hb1 = __floats2half2_rn(ab.z * inv, ab.w * inv);
    ((uint2*)out_a)[(size_t)n * 32 + lane] = make_uint2(*(unsigned*)&ha0, *(unsigned*)&ha1);
    ((uint2*)out_b)[(size_t)n * 32 + lane] = make_uint2(*(unsigned*)&hb0, *(unsigned*)&hb1);
}

// ======== tensor-core GEMM x3 (one launch): out_f32 = relu(xh @ Wh^T + b) ========
#define APITCH 136
#define MMA_SMEM (2 * 128 * APITCH * 2)

__device__ __forceinline__ unsigned smem_u32p(const void* p) {
    return (unsigned)__cvta_generic_to_shared(p);
}

struct Gemm3 {
    const __half* x[3];
    const float*  b[3];
    float*        y[3];
};

__global__ void __launch_bounds__(256, 2)
k_gemm_mma3(Gemm3 jobs, const __half* __restrict__ WhBase, int N)
{
    extern __shared__ __half smh[];
    __half* As = smh;                  // [128][APITCH]
    __half* Bs = smh + 128 * APITCH;   // [128][APITCH]
    int tid = threadIdx.x;
    int lane = tid & 31, wid = tid >> 5;
    int row0 = blockIdx.x * 128;
    int jz = blockIdx.y;
    const __half* xh = jobs.x[jz];
    const __half* Wh = WhBase + jz * DD * DD;
    const float* bias = jobs.b[jz];
    float* out = jobs.y[jz];

    for (int i = tid; i < 128 * 16; i += 256) {
        int r = i >> 4, c = i & 15;
        uint4 v = *((const uint4*)(Wh + r * DD) + c);
        *(uint4*)(Bs + r * APITCH + c * 8) = v;
    }
    for (int i = tid; i < 128 * 16; i += 256) {
        int r = i >> 4, c = i & 15;
        int row = row0 + r;
        uint4 v = make_uint4(0u, 0u, 0u, 0u);
        if (row < N) v = *((const uint4*)(xh + (size_t)row * DD) + c);
        *(uint4*)(As + r * APITCH + c * 8) = v;
    }
    __syncthreads();

    float d[16][4];
#pragma unroll
    for (int t = 0; t < 16; t++) { d[t][0] = d[t][1] = d[t][2] = d[t][3] = 0.f; }

    int wm = wid * 16;
    int qr = lane & 7, q = lane >> 3;

#pragma unroll
    for (int kk = 0; kk < 8; kk++) {
        int arow = wm + qr + (q & 1) * 8;
        int acol = kk * 16 + (q >> 1) * 8;
        unsigned a0, a1, a2, a3;
        {
            unsigned addr = smem_u32p(As + arow * APITCH + acol);
            asm volatile("ldmatrix.sync.aligned.m8n8.x4.shared.b16 {%0,%1,%2,%3}, [%4];"
                         : "=r"(a0), "=r"(a1), "=r"(a2), "=r"(a3) : "r"(addr));
        }
#pragma unroll
        for (int bt = 0; bt < 8; bt++) {
            int brow = bt * 16 + qr + (q >> 1) * 8;
            int bcol = kk * 16 + (q & 1) * 8;
            unsigned b0, b1, b2, b3;
            unsigned addr = smem_u32p(Bs + brow * APITCH + bcol);
            asm volatile("ldmatrix.sync.aligned.m8n8.x4.shared.b16 {%0,%1,%2,%3}, [%4];"
                         : "=r"(b0), "=r"(b1), "=r"(b2), "=r"(b3) : "r"(addr));
            float* dt0 = d[2 * bt];
            asm volatile("mma.sync.aligned.m16n8k16.row.col.f32.f16.f16.f32 "
                         "{%0,%1,%2,%3}, {%4,%5,%6,%7}, {%8,%9}, {%0,%1,%2,%3};"
                         : "+f"(dt0[0]), "+f"(dt0[1]), "+f"(dt0[2]), "+f"(dt0[3])
                         : "r"(a0), "r"(a1), "r"(a2), "r"(a3), "r"(b0), "r"(b1));
            float* dt1 = d[2 * bt + 1];
            asm volatile("mma.sync.aligned.m16n8k16.row.col.f32.f16.f16.f32 "
                         "{%0,%1,%2,%3}, {%4,%5,%6,%7}, {%8,%9}, {%0,%1,%2,%3};"
                         : "+f"(dt1[0]), "+f"(dt1[1]), "+f"(dt1[2]), "+f"(dt1[3])
                         : "r"(a0), "r"(a1), "r"(a2), "r"(a3), "r"(b2), "r"(b3));
        }
    }

    int r_lo = row0 + wm + (lane >> 2);
    int cbase = (lane & 3) * 2;
#pragma unroll
    for (int t = 0; t < 16; t++) {
        int col = t * 8 + cbase;
        float bb0 = __ldg(bias + col), bb1 = __ldg(bias + col + 1);
        if (r_lo < N) {
            float2 v = make_float2(fmaxf(d[t][0] + bb0, 0.f), fmaxf(d[t][1] + bb1, 0.f));
            *(float2*)(out + (size_t)r_lo * DD + col) = v;
        }
        if (r_lo + 8 < N) {
            float2 v = make_float2(fmaxf(d[t][2] + bb0, 0.f), fmaxf(d[t][3] + bb1, 0.f));
            *(float2*)(out + (size_t)(r_lo + 8) * DD + col) = v;
        }
    }
}

// ---------------- attention combine ----------------
__global__ void k_att(const float* __restrict__ y1,
                      const float* __restrict__ y2,
                      const float* __restrict__ y3,
                      const float* __restrict__ att,
                      float* __restrict__ out,
                      int N)
{
    int t = blockIdx.x * blockDim.x + threadIdx.x;
    int n = t >> 5, lane = t & 31;
    if (n >= N) return;
    size_t base = (size_t)n * DD;
    float4 v1 = __ldg((const float4*)(y1 + base) + lane);
    float4 v2 = __ldg((const float4*)(y2 + base) + lane);
    float4 v3 = __ldg((const float4*)(y3 + base) + lane);
    float4 a1 = __ldg((const float4*)att + lane);
    float4 a2 = __ldg((const float4*)att + 32 + lane);
    float4 a3 = __ldg((const float4*)att + 64 + lane);

    float s1 = v1.x * a1.x + v1.y * a1.y + v1.z * a1.z + v1.w * a1.w;
    float s2 = v2.x * a2.x + v2.y * a2.y + v2.z * a2.z + v2.w * a2.w;
    float s3 = v3.x * a3.x + v3.y * a3.y + v3.z * a3.z + v3.w * a3.w;
#pragma unroll
    for (int off = 16; off; off >>= 1) {
        s1 += __shfl_xor_sync(0xFFFFFFFFu, s1, off);
        s2 += __shfl_xor_sync(0xFFFFFFFFu, s2, off);
        s3 += __shfl_xor_sync(0xFFFFFFFFu, s3, off);
    }
    float m = fmaxf(s1, fmaxf(s2, s3));
    float e1 = __expf(s1 - m), e2 = __expf(s2 - m), e3 = __expf(s3 - m);
    float inv = 1.0f / (e1 + e2 + e3);
    float w1 = e1 * inv, w2 = e2 * inv, w3 = e3 * inv;

    float4 o;
    o.x = w1 * v1.x + w2 * v2.x + w3 * v3.x;
    o.y = w1 * v1.y + w2 * v2.y + w3 * v3.y;
    o.z = w1 * v1.z + w2 * v2.z + w3 * v3.z;
    o.w = w1 * v1.w + w2 * v2.w + w3 * v3.w;
    ((float4*)(out + base))[lane] = o;
}

// ---------------- launch ----------------
static inline int cdiv(long long a, int b) { return (int)((a + b - 1) / b); }

extern "C" void kernel_launch(void* const* d_in, const int* in_sizes, int n_in,
                              void* d_out, int out_size)
{
    const float* x_node   = (const float*)d_in[0];
    const float* x1       = (const float*)d_in[1];
    const float* x2       = (const float*)d_in[2];
    const int*   ei1_src  = (const int*)d_in[3];
    const int*   ei1_dst  = (const int*)d_in[4];
    const int*   ei2_src  = (const int*)d_in[5];
    const int*   ei2_dst  = (const int*)d_in[6];
    const int*   ei12_src = (const int*)d_in[7];
    const int*   ei12_dst = (const int*)d_in[8];
    const float* ew1      = (const float*)d_in[9];
    const float* ew2      = (const float*)d_in[10];
    const float* W1       = (const float*)d_in[11];
    const float* b1       = (const float*)d_in[12];
    const float* W2       = (const float*)d_in[13];
    const float* b2       = (const float*)d_in[14];
    const float* W12      = (const float*)d_in[15];
    const float* b12      = (const float*)d_in[16];
    const float* att      = (const float*)d_in[17];
    float* out = (float*)d_out;

    int n0  = in_sizes[0] / DD;
    int n1  = in_sizes[1] / DD;
    int n2  = in_sizes[2] / DD;
    int e1  = in_sizes[3];
    int e2  = in_sizes[5];
    int e12 = in_sizes[7];

    __half *xnodeh, *net1h, *net2h, *net2bh, *s1h, *s2h, *s12h, *Wh;
    float *s1, *s2, *s12;
    int *rowptr, *cursor, *pb1g, *pcg;
    int2 *p1gw, *p2gw, *pb2gw;
    cudaGetSymbolAddress((void**)&xnodeh, g_xnodeh);
    cudaGetSymbolAddress((void**)&net1h,  g_net1h);
    cudaGetSymbolAddress((void**)&net2h,  g_net2h);
    cudaGetSymbolAddress((void**)&net2bh, g_net2bh);
    cudaGetSymbolAddress((void**)&s1h,  g_s1h);
    cudaGetSymbolAddress((void**)&s2h,  g_s2h);
    cudaGetSymbolAddress((void**)&s12h, g_s12h);
    cudaGetSymbolAddress((void**)&Wh,   g_Wh);
    cudaGetSymbolAddress((void**)&s1,  g_s1);
    cudaGetSymbolAddress((void**)&s2,  g_s2);
    cudaGetSymbolAddress((void**)&s12, g_s12);
    cudaGetSymbolAddress((void**)&rowptr, g_rowptr);
    cudaGetSymbolAddress((void**)&cursor, g_cursor);
    cudaGetSymbolAddress((void**)&p1gw,  g_p1gw);
    cudaGetSymbolAddress((void**)&p2gw,  g_p2gw);
    cudaGetSymbolAddress((void**)&pb2gw, g_pb2gw);
    cudaGetSymbolAddress((void**)&pb1g,  g_pb1g);
    cudaGetSymbolAddress((void**)&pcg,   g_pcg);

    cudaFuncSetAttribute(k_gemm_mma3, cudaFuncAttributeMaxDynamicSharedMemorySize, MMA_SMEM);

    cudaMemsetAsync(cursor, 0, (size_t)RPTOT * sizeof(int), 0);

    const int BT = 256;

    // --- conversions ---
    k_f2h<<<cdiv((long long)n0 * 32, BT), BT>>>(x_node, xnodeh, n0 * 32);
    k_f2h3<<<cdiv(3 * DD * DD / 4, BT), BT>>>(W1, W2, W12, Wh);

    // --- histograms ---
    k_hist<<<cdiv(e1, BT), BT>>>(ei1_dst,   cursor + RP1,  e1);
    k_hist<<<cdiv(e2, BT), BT>>>(ei2_dst,   cursor + RP2,  e2);
    k_hist<<<cdiv(e1, BT), BT>>>(ei1_src,   cursor + RPB1, e1);
    k_hist<<<cdiv(e12, BT), BT>>>(ei12_dst, cursor + RPC,  e12);
    k_hist<<<cdiv(e2, BT), BT>>>(ei2_src,   cursor + RPB2, e2);

    // --- fused scans ---
    Seg5 segs;
    segs.off[0] = RP1;  segs.n[0] = n1;
    segs.off[1] = RP2;  segs.n[1] = n2;
    segs.off[2] = RPB1; segs.n[2] = n0;
    segs.off[3] = RPC;  segs.n[3] = n2;
    segs.off[4] = RPB2; segs.n[4] = n0;
    k_scan5<<<5, 1024>>>(rowptr, cursor, segs);

    // --- binning ---
    k_bin_w<<<cdiv(e1, BT), BT>>>(ei1_dst,  ei1_src,  ew1, cursor + RP1,  p1gw,  e1);
    k_bin_w<<<cdiv(e2, BT), BT>>>(ei2_dst,  ei2_src,  ew2, cursor + RP2,  p2gw,  e2);
    k_bin_u<<<cdiv(e1, BT), BT>>>(ei1_src,  ei1_dst,  cursor + RPB1, pb1g, e1);
    k_bin_u<<<cdiv(e12, BT), BT>>>(ei12_dst, ei12_src, cursor + RPC,  pcg,  e12);
    k_bin_w<<<cdiv(e2, BT), BT>>>(ei2_src,  ei2_dst,  ew2, cursor + RPB2, pb2gw, e2);

    // --- gathers (R11 shapes) ---
    k_gather_msg_h16<<<cdiv((long long)n1 * 32, BT), BT>>>(xnodeh, p1gw, rowptr + RP1, x1, net1h, n1);
    k_gather_msg_h16<<<cdiv((long long)n2 * 32, BT), BT>>>(xnodeh, p2gw, rowptr + RP2, x2, net2h, n2);
    k_gather_s_h<<<cdiv((long long)n0 * 32, BT), BT>>>(net1h, pb1g, rowptr + RPB1, s1h, n0);
    k_gather_msg_hh<<<cdiv((long long)n2 * 32, BT), BT>>>(net1h, pcg, rowptr + RPC, x2, net2bh, n2);
    k_gather_dual_h<<<cdiv((long long)n0 * 32, BT), BT>>>(net2h, net2bh, pb2gw, rowptr + RPB2, s2h, s12h, n0);

    // --- tensor-core GEMM x3 in one launch ---
    {
        Gemm3 g;
        g.x[0] = s1h;  g.b[0] = b1;  g.y[0] = s1;
        g.x[1] = s2h;  g.b[1] = b2;  g.y[1] = s2;
        g.x[2] = s12h; g.b[2] = b12; g.y[2] = s12;
        dim3 grid(cdiv(n0, 128), 3);
        k_gemm_mma3<<<grid, 256, MMA_SMEM>>>(g, Wh, n0);
    }

    // --- attention combine ---
    k_att<<<cdiv((long long)n0 * 32, BT), BT>>>(s1, s2, s12, att, out, n0);
}

// round 15
// speedup vs baseline: 1.3998x; 1.0008x over previous
#include <cuda_runtime.h>
#include <cuda_fp16.h>
#include <cstdint>
#include <math.h>

#define DD 128
#define N0CAP 100000
#define N1CAP 50000
#define N2CAP 50000
#define E1CAP 1600000
#define E2CAP 1600000
#define E12CAP 800000

// ---------------- scratch ----------------
__device__ __half g_xnodeh[N0CAP * DD];
__device__ __half g_net1h [N1CAP * DD];
__device__ __half g_net2h [N2CAP * DD];
__device__ __half g_net2bh[N2CAP * DD];
__device__ __half g_s1h[N0CAP * DD];
__device__ __half g_s2h[N0CAP * DD];
__device__ __half g_s12h[N0CAP * DD];
__device__ __half g_Wh[3 * DD * DD];
__device__ float  g_s1 [N0CAP * DD];
__device__ float  g_s2 [N0CAP * DD];
__device__ float  g_s12[N0CAP * DD];

#define RP1   0
#define RP2   (RP1 + N1CAP + 1)
#define RPB1  (RP2 + N2CAP + 1)
#define RPC   (RPB1 + N0CAP + 1)
#define RPB2  (RPC + N2CAP + 1)
#define RPTOT (RPB2 + N0CAP + 1)
__device__ int g_rowptr[RPTOT];
__device__ int g_cursor[RPTOT];   // doubles as histogram

__device__ int2 g_p1gw [E1CAP];   // (gather idx, weight bits)
__device__ int2 g_p2gw [E2CAP];
__device__ int2 g_pb2gw[E2CAP];
__device__ int  g_pb1g [E1CAP];
__device__ int  g_pcg  [E12CAP];

// ---------------- fp32 -> fp16 conversion ----------------
__global__ void k_f2h(const float* __restrict__ src, __half* __restrict__ dst, int n4)
{
    int t = blockIdx.x * blockDim.x + threadIdx.x;
    if (t >= n4) return;
    float4 v = __ldg((const float4*)src + t);
    __half2 h0 = __floats2half2_rn(v.x, v.y);
    __half2 h1 = __floats2half2_rn(v.z, v.w);
    ((uint2*)dst)[t] = make_uint2(*(unsigned*)&h0, *(unsigned*)&h1);
}

// 3 weight matrices in one launch
__global__ void k_f2h3(const float* __restrict__ w1, const float* __restrict__ w2,
                       const float* __restrict__ w3, __half* __restrict__ dst)
{
    int t = blockIdx.x * blockDim.x + threadIdx.x;
    const int per = DD * DD / 4;
    if (t >= 3 * per) return;
    int m = t / per, i = t - m * per;
    const float* src = (m == 0) ? w1 : (m == 1) ? w2 : w3;
    float4 v = __ldg((const float4*)src + i);
    __half2 h0 = __floats2half2_rn(v.x, v.y);
    __half2 h1 = __floats2half2_rn(v.z, v.w);
    ((uint2*)dst)[t] = make_uint2(*(unsigned*)&h0, *(unsigned*)&h1);
}

// ---------------- histogram, 4 edges per thread (ILP) ----------------
__global__ void k_hist4(const int* __restrict__ idx, int* __restrict__ hist, int E)
{
    int t = blockIdx.x * blockDim.x + threadIdx.x;
    int e0 = t * 4;
    if (e0 + 4 <= E) {
        int4 v = __ldg((const int4*)(idx + e0));
        atomicAdd(hist + v.x, 1);
        atomicAdd(hist + v.y, 1);
        atomicAdd(hist + v.z, 1);
        atomicAdd(hist + v.w, 1);
    } else {
        for (int e = e0; e < E; e++) atomicAdd(hist + __ldg(idx + e), 1);
    }
}

// ---------------- fused exclusive scan over 5 segments ----------------
struct Seg5 { int off[5]; int n[5]; };
__global__ void k_scan5(int* __restrict__ rowptr_base, int* __restrict__ cur_base, Seg5 segs)
{
    __shared__ int wsum[32];
    int off = segs.off[blockIdx.x];
    int N   = segs.n[blockIdx.x];
    int* hist = cur_base + off;
    int* rp   = rowptr_base + off;

    int tid = threadIdx.x;                 // blockDim = 1024
    int per = (N + 1023) >> 10;
    int lo = tid * per; if (lo > N) lo = N;
    int hi = lo + per;  if (hi > N) hi = N;

    int sum = 0;
    for (int i = lo; i < hi; i++) sum += hist[i];

    int lane = tid & 31, wid = tid >> 5;
    int v = sum;
#pragma unroll
    for (int o = 1; o < 32; o <<= 1) {
        int t = __shfl_up_sync(0xffffffffu, v, o);
        if (lane >= o) v += t;
    }
    if (lane == 31) wsum[wid] = v;
    __syncthreads();
    if (wid == 0) {
        int s = wsum[lane];
#pragma unroll
        for (int o = 1; o < 32; o <<= 1) {
            int t = __shfl_up_sync(0xffffffffu, s, o);
            if (lane >= o) s += t;
        }
        wsum[lane] = s;
    }
    __syncthreads();
    int excl = (v - sum) + (wid ? wsum[wid - 1] : 0);

    int run = excl;
    for (int i = lo; i < hi; i++) {
        int c = hist[i];
        rp[i] = run;
        hist[i] = run;
        run += c;
    }
    if (tid == 1023) rp[N] = excl + sum;
}

// ---------------- binning, 4 edges per thread (ILP) ----------------
__global__ void k_bin_w4(const int*   __restrict__ sc_idx,
                         const int*   __restrict__ g_idx,
                         const float* __restrict__ ew,
                         int*  __restrict__ cursor,
                         int2* __restrict__ pgw,
                         int E)
{
    int t = blockIdx.x * blockDim.x + threadIdx.x;
    int e0 = t * 4;
    if (e0 + 4 <= E) {
        int4 b = __ldg((const int4*)(sc_idx + e0));
        int4 g = __ldg((const int4*)(g_idx + e0));
        float4 w = __ldg((const float4*)(ew + e0));
        int p0 = atomicAdd(cursor + b.x, 1);
        int p1 = atomicAdd(cursor + b.y, 1);
        int p2 = atomicAdd(cursor + b.z, 1);
        int p3 = atomicAdd(cursor + b.w, 1);
        pgw[p0] = make_int2(g.x, __float_as_int(w.x));
        pgw[p1] = make_int2(g.y, __float_as_int(w.y));
        pgw[p2] = make_int2(g.z, __float_as_int(w.z));
        pgw[p3] = make_int2(g.w, __float_as_int(w.w));
    } else {
        for (int e = e0; e < E; e++) {
            int b = __ldg(sc_idx + e);
            int p = atomicAdd(cursor + b, 1);
            pgw[p] = make_int2(__ldg(g_idx + e), __float_as_int(__ldg(ew + e)));
        }
    }
}

__global__ void k_bin_u4(const int* __restrict__ sc_idx,
                         const int* __restrict__ g_idx,
                         int* __restrict__ cursor,
                         int* __restrict__ pg,
                         int E)
{
    int t = blockIdx.x * blockDim.x + threadIdx.x;
    int e0 = t * 4;
    if (e0 + 4 <= E) {
        int4 b = __ldg((const int4*)(sc_idx + e0));
        int4 g = __ldg((const int4*)(g_idx + e0));
        int p0 = atomicAdd(cursor + b.x, 1);
        int p1 = atomicAdd(cursor + b.y, 1);
        int p2 = atomicAdd(cursor + b.z, 1);
        int p3 = atomicAdd(cursor + b.w, 1);
        pg[p0] = g.x;
        pg[p1] = g.y;
        pg[p2] = g.z;
        pg[p3] = g.w;
    } else {
        for (int e = e0; e < E; e++) {
            int b = __ldg(sc_idx + e);
            int p = atomicAdd(cursor + b, 1);
            pg[p] = __ldg(g_idx + e);
        }
    }
}

// ======== gather A: fp16 src, weighted(packed), out = half((mean + xb)*0.5) [MLP4] ========
__global__ void k_gather_msg_h16(const __half* __restrict__ feath,
                                 const int2*   __restrict__ pgw,
                                 const int*    __restrict__ rp,
                                 const float*  __restrict__ xb,
                                 __half* __restrict__ outh,
                                 int N)
{
    int t = blockIdx.x * blockDim.x + threadIdx.x;
    int n = t >> 5, lane = t & 31;
    if (n >= N) return;
    int start = __ldg(rp + n), end = __ldg(rp + n + 1);
    const uint2* fb = (const uint2*)feath;

    float4 acc = make_float4(0.f, 0.f, 0.f, 0.f);
    int j = start;
    for (; j + 4 <= end; j += 4) {
        int2 e0 = __ldg(pgw + j),     e1 = __ldg(pgw + j + 1);
        int2 e2 = __ldg(pgw + j + 2), e3 = __ldg(pgw + j + 3);
        uint2 u0 = __ldg(fb + (size_t)e0.x * 32 + lane);
        uint2 u1 = __ldg(fb + (size_t)e1.x * 32 + lane);
        uint2 u2 = __ldg(fb + (size_t)e2.x * 32 + lane);
        uint2 u3 = __ldg(fb + (size_t)e3.x * 32 + lane);
        float w0 = __int_as_float(e0.y), w1 = __int_as_float(e1.y);
        float w2 = __int_as_float(e2.y), w3 = __int_as_float(e3.y);
#pragma unroll
        for (int q = 0; q < 4; q++) {
            uint2 u = (q == 0) ? u0 : (q == 1) ? u1 : (q == 2) ? u2 : u3;
            float w = (q == 0) ? w0 : (q == 1) ? w1 : (q == 2) ? w2 : w3;
            float2 f0 = __half22float2(*(__half2*)&u.x);
            float2 f1 = __half22float2(*(__half2*)&u.y);
            acc.x += f0.x * w; acc.y += f0.y * w;
            acc.z += f1.x * w; acc.w += f1.y * w;
        }
    }
    for (; j < end; j++) {
        int2 e = __ldg(pgw + j);
        float w = __int_as_float(e.y);
        uint2 u = __ldg(fb + (size_t)e.x * 32 + lane);
        float2 f0 = __half22float2(*(__half2*)&u.x);
        float2 f1 = __half22float2(*(__half2*)&u.y);
        acc.x += f0.x * w; acc.y += f0.y * w; acc.z += f1.x * w; acc.w += f1.y * w;
    }
    int deg = end - start;
    float inv = 1.0f / (deg > 1 ? (float)deg : 1.0f);
    float4 x = __ldg((const float4*)(xb + (size_t)n * DD) + lane);
    float4 r;
    r.x = (acc.x * inv + x.x) * 0.5f;
    r.y = (acc.y * inv + x.y) * 0.5f;
    r.z = (acc.z * inv + x.z) * 0.5f;
    r.w = (acc.w * inv + x.w) * 0.5f;
    __half2 h0 = __floats2half2_rn(r.x, r.y);
    __half2 h1 = __floats2half2_rn(r.z, r.w);
    ((uint2*)outh)[(size_t)n * 32 + lane] = make_uint2(*(unsigned*)&h0, *(unsigned*)&h1);
}

// ======== gather B: fp16 src, unweighted, out = half(mean) [MLP4] ========
__global__ void k_gather_s_h(const __half* __restrict__ feath,
                             const int*    __restrict__ pg,
                             const int*    __restrict__ rp,
                             __half* __restrict__ outh,
                             int N)
{
    int t = blockIdx.x * blockDim.x + threadIdx.x;
    int n = t >> 5, lane = t & 31;
    if (n >= N) return;
    int start = __ldg(rp + n), end = __ldg(rp + n + 1);
    const uint2* fb = (const uint2*)feath;

    float4 acc = make_float4(0.f, 0.f, 0.f, 0.f);
    int j = start;
    for (; j + 4 <= end; j += 4) {
        int g0 = __ldg(pg + j), g1 = __ldg(pg + j + 1);
        int g2 = __ldg(pg + j + 2), g3 = __ldg(pg + j + 3);
        uint2 u0 = __ldg(fb + (size_t)g0 * 32 + lane);
        uint2 u1 = __ldg(fb + (size_t)g1 * 32 + lane);
        uint2 u2 = __ldg(fb + (size_t)g2 * 32 + lane);
        uint2 u3 = __ldg(fb + (size_t)g3 * 32 + lane);
#pragma unroll
        for (int q = 0; q < 4; q++) {
            uint2 u = (q == 0) ? u0 : (q == 1) ? u1 : (q == 2) ? u2 : u3;
            float2 f0 = __half22float2(*(__half2*)&u.x);
            float2 f1 = __half22float2(*(__half2*)&u.y);
            acc.x += f0.x; acc.y += f0.y; acc.z += f1.x; acc.w += f1.y;
        }
    }
    for (; j < end; j++) {
        int g = __ldg(pg + j);
        uint2 u = __ldg(fb + (size_t)g * 32 + lane);
        float2 f0 = __half22float2(*(__half2*)&u.x);
        float2 f1 = __half22float2(*(__half2*)&u.y);
        acc.x += f0.x; acc.y += f0.y; acc.z += f1.x; acc.w += f1.y;
    }
    int deg = end - start;
    float inv = 1.0f / (deg > 1 ? (float)deg : 1.0f);
    __half2 h0 = __floats2half2_rn(acc.x * inv, acc.y * inv);
    __half2 h1 = __floats2half2_rn(acc.z * inv, acc.w * inv);
    ((uint2*)outh)[(size_t)n * 32 + lane] = make_uint2(*(unsigned*)&h0, *(unsigned*)&h1);
}

// ======== gather C: fp16 src, unweighted, out = half((mean + xb)*0.5) [MLP4] ========
__global__ void k_gather_msg_hh(const __half* __restrict__ feath,
                                const int*    __restrict__ pg,
                                const int*    __restrict__ rp,
                                const float*  __restrict__ xb,
                                __half* __restrict__ outh,
                                int N)
{
    int t = blockIdx.x * blockDim.x + threadIdx.x;
    int n = t >> 5, lane = t & 31;
    if (n >= N) return;
    int start = __ldg(rp + n), end = __ldg(rp + n + 1);
    const uint2* fb = (const uint2*)feath;

    float4 acc = make_float4(0.f, 0.f, 0.f, 0.f);
    int j = start;
    for (; j + 4 <= end; j += 4) {
        int g0 = __ldg(pg + j), g1 = __ldg(pg + j + 1);
        int g2 = __ldg(pg + j + 2), g3 = __ldg(pg + j + 3);
        uint2 u0 = __ldg(fb + (size_t)g0 * 32 + lane);
        uint2 u1 = __ldg(fb + (size_t)g1 * 32 + lane);
        uint2 u2 = __ldg(fb + (size_t)g2 * 32 + lane);
        uint2 u3 = __ldg(fb + (size_t)g3 * 32 + lane);
#pragma unroll
        for (int q = 0; q < 4; q++) {
            uint2 u = (q == 0) ? u0 : (q == 1) ? u1 : (q == 2) ? u2 : u3;
            float2 f0 = __half22float2(*(__half2*)&u.x);
            float2 f1 = __half22float2(*(__half2*)&u.y);
            acc.x += f0.x; acc.y += f0.y; acc.z += f1.x; acc.w += f1.y;
        }
    }
    for (; j < end; j++) {
        int g = __ldg(pg + j);
        uint2 u = __ldg(fb + (size_t)g * 32 + lane);
        float2 f0 = __half22float2(*(__half2*)&u.x);
        float2 f1 = __half22float2(*(__half2*)&u.y);
        acc.x += f0.x; acc.y += f0.y; acc.z += f1.x; acc.w += f1.y;
    }
    int deg = end - start;
    float inv = 1.0f / (deg > 1 ? (float)deg : 1.0f);
    float4 x = __ldg((const float4*)(xb + (size_t)n * DD) + lane);
    float4 r;
    r.x = (acc.x * inv + x.x) * 0.5f;
    r.y = (acc.y * inv + x.y) * 0.5f;
    r.z = (acc.z * inv + x.z) * 0.5f;
    r.w = (acc.w * inv + x.w) * 0.5f;
    __half2 h0 = __floats2half2_rn(r.x, r.y);
    __half2 h1 = __floats2half2_rn(r.z, r.w);
    ((uint2*)outh)[(size_t)n * 32 + lane] = make_uint2(*(unsigned*)&h0, *(unsigned*)&h1);
}

// ======== dual gather: fp16 srcs, packed weight (b only), half outs [2-edge] ========
__global__ void k_gather_dual_h(const __half* __restrict__ feat_a,
                                const __half* __restrict__ feat_b,
                                const int2*   __restrict__ pgw,
                                const int*    __restrict__ rp,
                                __half* __restrict__ out_a,
                                __half* __restrict__ out_b,
                                int N)
{
    int t = blockIdx.x * blockDim.x + threadIdx.x;
    int n = t >> 5, lane = t & 31;
    if (n >= N) return;
    int start = __ldg(rp + n), end = __ldg(rp + n + 1);
    const uint2* fa = (const uint2*)feat_a;
    const uint2* fbp = (const uint2*)feat_b;

    float4 aa = make_float4(0.f, 0.f, 0.f, 0.f);
    float4 ab = make_float4(0.f, 0.f, 0.f, 0.f);
    int j = start;
    for (; j + 2 <= end; j += 2) {
        int2 e0 = __ldg(pgw + j), e1 = __ldg(pgw + j + 1);
        uint2 a0 = __ldg(fa  + (size_t)e0.x * 32 + lane);
        uint2 b0 = __ldg(fbp + (size_t)e0.x * 32 + lane);
        uint2 a1 = __ldg(fa  + (size_t)e1.x * 32 + lane);
        uint2 b1 = __ldg(fbp + (size_t)e1.x * 32 + lane);
        float w0 = __int_as_float(e0.y), w1 = __int_as_float(e1.y);
        {
            float2 f0 = __half22float2(*(__half2*)&a0.x);
            float2 f1 = __half22float2(*(__half2*)&a0.y);
            float2 g0 = __half22float2(*(__half2*)&a1.x);
            float2 g1 = __half22float2(*(__half2*)&a1.y);
            aa.x += f0.x + g0.x; aa.y += f0.y + g0.y;
            aa.z += f1.x + g1.x; aa.w += f1.y + g1.y;
        }
        {
            float2 f0 = __half22float2(*(__half2*)&b0.x);
            float2 f1 = __half22float2(*(__half2*)&b0.y);
            float2 g0 = __half22float2(*(__half2*)&b1.x);
            float2 g1 = __half22float2(*(__half2*)&b1.y);
            ab.x += f0.x * w0 + g0.x * w1; ab.y += f0.y * w0 + g0.y * w1;
            ab.z += f1.x * w0 + g1.x * w1; ab.w += f1.y * w0 + g1.y * w1;
        }
    }
    for (; j < end; j++) {
        int2 e = __ldg(pgw + j);
        float w = __int_as_float(e.y);
        uint2 a = __ldg(fa  + (size_t)e.x * 32 + lane);
        uint2 b = __ldg(fbp + (size_t)e.x * 32 + lane);
        float2 f0 = __half22float2(*(__half2*)&a.x);
        float2 f1 = __half22float2(*(__half2*)&a.y);
        aa.x += f0.x; aa.y += f0.y; aa.z += f1.x; aa.w += f1.y;
        float2 h0 = __half22float2(*(__half2*)&b.x);
        float2 h1 = __half22float2(*(__half2*)&b.y);
        ab.x += h0.x * w; ab.y += h0.y * w; ab.z += h1.x * w; ab.w += h1.y * w;
    }
    int deg = end - start;
    float inv = 1.0f / (deg > 1 ? (float)deg : 1.0f);
    __half2 ha0 = __floats2half2_rn(aa.x * inv, aa.y * inv);
    __half2 ha1 = __floats2half2_rn(aa.z * inv, aa.w * inv);
    __half2 hb0 = __floats2half2_rn(ab.x * inv, ab.y * inv);
    __half2 hb1 = __floats2half2_rn(ab.z * inv, ab.w * inv);
    ((uint2*)out_a)[(size_t)n * 32 + lane] = make_uint2(*(unsigned*)&ha0, *(unsigned*)&ha1);
    ((uint2*)out_b)[(size_t)n * 32 + lane] = make_uint2(*(unsigned*)&hb0, *(unsigned*)&hb1);
}

// ======== tensor-core GEMM x3 (one launch): out_f32 = relu(xh @ Wh^T + b) ========
#define APITCH 136
#define MMA_SMEM (2 * 128 * APITCH * 2)

__device__ __forceinline__ unsigned smem_u32p(const void* p) {
    return (unsigned)__cvta_generic_to_shared(p);
}

struct Gemm3 {
    const __half* x[3];
    const float*  b[3];
    float*        y[3];
};

__global__ void __launch_bounds__(256, 2)
k_gemm_mma3(Gemm3 jobs, const __half* __restrict__ WhBase, int N)
{
    extern __shared__ __half smh[];
    __half* As = smh;                  // [128][APITCH]
    __half* Bs = smh + 128 * APITCH;   // [128][APITCH]
    int tid = threadIdx.x;
    int lane = tid & 31, wid = tid >> 5;
    int row0 = blockIdx.x * 128;
    int jz = blockIdx.y;
    const __half* xh = jobs.x[jz];
    const __half* Wh = WhBase + jz * DD * DD;
    const float* bias = jobs.b[jz];
    float* out = jobs.y[jz];

    for (int i = tid; i < 128 * 16; i += 256) {
        int r = i >> 4, c = i & 15;
        uint4 v = *((const uint4*)(Wh + r * DD) + c);
        *(uint4*)(Bs + r * APITCH + c * 8) = v;
    }
    for (int i = tid; i < 128 * 16; i += 256) {
        int r = i >> 4, c = i & 15;
        int row = row0 + r;
        uint4 v = make_uint4(0u, 0u, 0u, 0u);
        if (row < N) v = *((const uint4*)(xh + (size_t)row * DD) + c);
        *(uint4*)(As + r * APITCH + c * 8) = v;
    }
    __syncthreads();

    float d[16][4];
#pragma unroll
    for (int t = 0; t < 16; t++) { d[t][0] = d[t][1] = d[t][2] = d[t][3] = 0.f; }

    int wm = wid * 16;
    int qr = lane & 7, q = lane >> 3;

#pragma unroll
    for (int kk = 0; kk < 8; kk++) {
        int arow = wm + qr + (q & 1) * 8;
        int acol = kk * 16 + (q >> 1) * 8;
        unsigned a0, a1, a2, a3;
        {
            unsigned addr = smem_u32p(As + arow * APITCH + acol);
            asm volatile("ldmatrix.sync.aligned.m8n8.x4.shared.b16 {%0,%1,%2,%3}, [%4];"
                         : "=r"(a0), "=r"(a1), "=r"(a2), "=r"(a3) : "r"(addr));
        }
#pragma unroll
        for (int bt = 0; bt < 8; bt++) {
            int brow = bt * 16 + qr + (q >> 1) * 8;
            int bcol = kk * 16 + (q & 1) * 8;
            unsigned b0, b1, b2, b3;
            unsigned addr = smem_u32p(Bs + brow * APITCH + bcol);
            asm volatile("ldmatrix.sync.aligned.m8n8.x4.shared.b16 {%0,%1,%2,%3}, [%4];"
                         : "=r"(b0), "=r"(b1), "=r"(b2), "=r"(b3) : "r"(addr));
            float* dt0 = d[2 * bt];
            asm volatile("mma.sync.aligned.m16n8k16.row.col.f32.f16.f16.f32 "
                         "{%0,%1,%2,%3}, {%4,%5,%6,%7}, {%8,%9}, {%0,%1,%2,%3};"
                         : "+f"(dt0[0]), "+f"(dt0[1]), "+f"(dt0[2]), "+f"(dt0[3])
                         : "r"(a0), "r"(a1), "r"(a2), "r"(a3), "r"(b0), "r"(b1));
            float* dt1 = d[2 * bt + 1];
            asm volatile("mma.sync.aligned.m16n8k16.row.col.f32.f16.f16.f32 "
                         "{%0,%1,%2,%3}, {%4,%5,%6,%7}, {%8,%9}, {%0,%1,%2,%3};"
                         : "+f"(dt1[0]), "+f"(dt1[1]), "+f"(dt1[2]), "+f"(dt1[3])
                         : "r"(a0), "r"(a1), "r"(a2), "r"(a3), "r"(b2), "r"(b3));
        }
    }

    int r_lo = row0 + wm + (lane >> 2);
    int cbase = (lane & 3) * 2;
#pragma unroll
    for (int t = 0; t < 16; t++) {
        int col = t * 8 + cbase;
        float bb0 = __ldg(bias + col), bb1 = __ldg(bias + col + 1);
        if (r_lo < N) {
            float2 v = make_float2(fmaxf(d[t][0] + bb0, 0.f), fmaxf(d[t][1] + bb1, 0.f));
            *(float2*)(out + (size_t)r_lo * DD + col) = v;
        }
        if (r_lo + 8 < N) {
            float2 v = make_float2(fmaxf(d[t][2] + bb0, 0.f), fmaxf(d[t][3] + bb1, 0.f));
            *(float2*)(out + (size_t)(r_lo + 8) * DD + col) = v;
        }
    }
}

// ---------------- attention combine ----------------
__global__ void k_att(const float* __restrict__ y1,
                      const float* __restrict__ y2,
                      const float* __restrict__ y3,
                      const float* __restrict__ att,
                      float* __restrict__ out,
                      int N)
{
    int t = blockIdx.x * blockDim.x + threadIdx.x;
    int n = t >> 5, lane = t & 31;
    if (n >= N) return;
    size_t base = (size_t)n * DD;
    float4 v1 = __ldg((const float4*)(y1 + base) + lane);
    float4 v2 = __ldg((const float4*)(y2 + base) + lane);
    float4 v3 = __ldg((const float4*)(y3 + base) + lane);
    float4 a1 = __ldg((const float4*)att + lane);
    float4 a2 = __ldg((const float4*)att + 32 + lane);
    float4 a3 = __ldg((const float4*)att + 64 + lane);

    float s1 = v1.x * a1.x + v1.y * a1.y + v1.z * a1.z + v1.w * a1.w;
    float s2 = v2.x * a2.x + v2.y * a2.y + v2.z * a2.z + v2.w * a2.w;
    float s3 = v3.x * a3.x + v3.y * a3.y + v3.z * a3.z + v3.w * a3.w;
#pragma unroll
    for (int off = 16; off; off >>= 1) {
        s1 += __shfl_xor_sync(0xFFFFFFFFu, s1, off);
        s2 += __shfl_xor_sync(0xFFFFFFFFu, s2, off);
        s3 += __shfl_xor_sync(0xFFFFFFFFu, s3, off);
    }
    float m = fmaxf(s1, fmaxf(s2, s3));
    float e1 = __expf(s1 - m), e2 = __expf(s2 - m), e3 = __expf(s3 - m);
    float inv = 1.0f / (e1 + e2 + e3);
    float w1 = e1 * inv, w2 = e2 * inv, w3 = e3 * inv;

    float4 o;
    o.x = w1 * v1.x + w2 * v2.x + w3 * v3.x;
    o.y = w1 * v1.y + w2 * v2.y + w3 * v3.y;
    o.z = w1 * v1.z + w2 * v2.z + w3 * v3.z;
    o.w = w1 * v1.w + w2 * v2.w + w3 * v3.w;
    ((float4*)(out + base))[lane] = o;
}

// ---------------- launch ----------------
static inline int cdiv(long long a, int b) { return (int)((a + b - 1) / b); }

extern "C" void kernel_launch(void* const* d_in, const int* in_sizes, int n_in,
                              void* d_out, int out_size)
{
    const float* x_node   = (const float*)d_in[0];
    const float* x1       = (const float*)d_in[1];
    const float* x2       = (const float*)d_in[2];
    const int*   ei1_src  = (const int*)d_in[3];
    const int*   ei1_dst  = (const int*)d_in[4];
    const int*   ei2_src  = (const int*)d_in[5];
    const int*   ei2_dst  = (const int*)d_in[6];
    const int*   ei12_src = (const int*)d_in[7];
    const int*   ei12_dst = (const int*)d_in[8];
    const float* ew1      = (const float*)d_in[9];
    const float* ew2      = (const float*)d_in[10];
    const float* W1       = (const float*)d_in[11];
    const float* b1       = (const float*)d_in[12];
    const float* W2       = (const float*)d_in[13];
    const float* b2       = (const float*)d_in[14];
    const float* W12      = (const float*)d_in[15];
    const float* b12      = (const float*)d_in[16];
    const float* att      = (const float*)d_in[17];
    float* out = (float*)d_out;

    int n0  = in_sizes[0] / DD;
    int n1  = in_sizes[1] / DD;
    int n2  = in_sizes[2] / DD;
    int e1  = in_sizes[3];
    int e2  = in_sizes[5];
    int e12 = in_sizes[7];

    __half *xnodeh, *net1h, *net2h, *net2bh, *s1h, *s2h, *s12h, *Wh;
    float *s1, *s2, *s12;
    int *rowptr, *cursor, *pb1g, *pcg;
    int2 *p1gw, *p2gw, *pb2gw;
    cudaGetSymbolAddress((void**)&xnodeh, g_xnodeh);
    cudaGetSymbolAddress((void**)&net1h,  g_net1h);
    cudaGetSymbolAddress((void**)&net2h,  g_net2h);
    cudaGetSymbolAddress((void**)&net2bh, g_net2bh);
    cudaGetSymbolAddress((void**)&s1h,  g_s1h);
    cudaGetSymbolAddress((void**)&s2h,  g_s2h);
    cudaGetSymbolAddress((void**)&s12h, g_s12h);
    cudaGetSymbolAddress((void**)&Wh,   g_Wh);
    cudaGetSymbolAddress((void**)&s1,  g_s1);
    cudaGetSymbolAddress((void**)&s2,  g_s2);
    cudaGetSymbolAddress((void**)&s12, g_s12);
    cudaGetSymbolAddress((void**)&rowptr, g_rowptr);
    cudaGetSymbolAddress((void**)&cursor, g_cursor);
    cudaGetSymbolAddress((void**)&p1gw,  g_p1gw);
    cudaGetSymbolAddress((void**)&p2gw,  g_p2gw);
    cudaGetSymbolAddress((void**)&pb2gw, g_pb2gw);
    cudaGetSymbolAddress((void**)&pb1g,  g_pb1g);
    cudaGetSymbolAddress((void**)&pcg,   g_pcg);

    cudaFuncSetAttribute(k_gemm_mma3, cudaFuncAttributeMaxDynamicSharedMemorySize, MMA_SMEM);

    cudaMemsetAsync(cursor, 0, (size_t)RPTOT * sizeof(int), 0);

    const int BT = 256;
    #define E4GRID(E) cdiv(((long long)(E) + 3) / 4, BT)

    // --- conversions ---
    k_f2h<<<cdiv((long long)n0 * 32, BT), BT>>>(x_node, xnodeh, n0 * 32);
    k_f2h3<<<cdiv(3 * DD * DD / 4, BT), BT>>>(W1, W2, W12, Wh);

    // --- histograms (ILP=4) ---
    k_hist4<<<E4GRID(e1), BT>>>(ei1_dst,   cursor + RP1,  e1);
    k_hist4<<<E4GRID(e2), BT>>>(ei2_dst,   cursor + RP2,  e2);
    k_hist4<<<E4GRID(e1), BT>>>(ei1_src,   cursor + RPB1, e1);
    k_hist4<<<E4GRID(e12), BT>>>(ei12_dst, cursor + RPC,  e12);
    k_hist4<<<E4GRID(e2), BT>>>(ei2_src,   cursor + RPB2, e2);

    // --- fused scans ---
    Seg5 segs;
    segs.off[0] = RP1;  segs.n[0] = n1;
    segs.off[1] = RP2;  segs.n[1] = n2;
    segs.off[2] = RPB1; segs.n[2] = n0;
    segs.off[3] = RPC;  segs.n[3] = n2;
    segs.off[4] = RPB2; segs.n[4] = n0;
    k_scan5<<<5, 1024>>>(rowptr, cursor, segs);

    // --- binning (ILP=4) ---
    k_bin_w4<<<E4GRID(e1), BT>>>(ei1_dst,  ei1_src,  ew1, cursor + RP1,  p1gw,  e1);
    k_bin_w4<<<E4GRID(e2), BT>>>(ei2_dst,  ei2_src,  ew2, cursor + RP2,  p2gw,  e2);
    k_bin_u4<<<E4GRID(e1), BT>>>(ei1_src,  ei1_dst,  cursor + RPB1, pb1g, e1);
    k_bin_u4<<<E4GRID(e12), BT>>>(ei12_dst, ei12_src, cursor + RPC,  pcg,  e12);
    k_bin_w4<<<E4GRID(e2), BT>>>(ei2_src,  ei2_dst,  ew2, cursor + RPB2, pb2gw, e2);

    // --- gathers (R11 shapes, frozen) ---
    k_gather_msg_h16<<<cdiv((long long)n1 * 32, BT), BT>>>(xnodeh, p1gw, rowptr + RP1, x1, net1h, n1);
    k_gather_msg_h16<<<cdiv((long long)n2 * 32, BT), BT>>>(xnodeh, p2gw, rowptr + RP2, x2, net2h, n2);
    k_gather_s_h<<<cdiv((long long)n0 * 32, BT), BT>>>(net1h, pb1g, rowptr + RPB1, s1h, n0);
    k_gather_msg_hh<<<cdiv((long long)n2 * 32, BT), BT>>>(net1h, pcg, rowptr + RPC, x2, net2bh, n2);
    k_gather_dual_h<<<cdiv((long long)n0 * 32, BT), BT>>>(net2h, net2bh, pb2gw, rowptr + RPB2, s2h, s12h, n0);

    // --- tensor-core GEMM x3 in one launch ---
    {
        Gemm3 g;
        g.x[0] = s1h;  g.b[0] = b1;  g.y[0] = s1;
        g.x[1] = s2h;  g.b[1] = b2;  g.y[1] = s2;
        g.x[2] = s12h; g.b[2] = b12; g.y[2] = s12;
        dim3 grid(cdiv(n0, 128), 3);
        k_gemm_mma3<<<grid, 256, MMA_SMEM>>>(g, Wh, n0);
    }

    // --- attention combine ---
    k_att<<<cdiv((long long)n0 * 32, BT), BT>>>(s1, s2, s12, att, out, n0);
}

// round 16
// speedup vs baseline: 1.4641x; 1.0460x over previous
#include <cuda_runtime.h>
#include <cuda_fp16.h>
#include <cstdint>
#include <math.h>

#define DD 128
#define N0CAP 100000
#define N1CAP 50000
#define N2CAP 50000
#define E1CAP 1600000
#define E2CAP 1600000
#define E12CAP 800000

// ---------------- scratch ----------------
__device__ __half g_xnodeh[N0CAP * DD];
__device__ __half g_net1h [N1CAP * DD];
__device__ __half g_net2h [N2CAP * DD];
__device__ __half g_net2bh[N2CAP * DD];
__device__ __half g_s1h[N0CAP * DD];
__device__ __half g_s2h[N0CAP * DD];
__device__ __half g_s12h[N0CAP * DD];
__device__ __half g_Wh[3 * DD * DD];

#define RP1   0
#define RP2   (RP1 + N1CAP + 1)
#define RPB1  (RP2 + N2CAP + 1)
#define RPC   (RPB1 + N0CAP + 1)
#define RPB2  (RPC + N2CAP + 1)
#define RPTOT (RPB2 + N0CAP + 1)
__device__ int g_rowptr[RPTOT];
__device__ int g_cursor[RPTOT];   // doubles as histogram

__device__ int2 g_p1gw [E1CAP];   // (gather idx, weight bits)
__device__ int2 g_p2gw [E2CAP];
__device__ int2 g_pb2gw[E2CAP];
__device__ int  g_pb1g [E1CAP];
__device__ int  g_pcg  [E12CAP];

// ---------------- fp32 -> fp16 conversion ----------------
__global__ void k_f2h(const float* __restrict__ src, __half* __restrict__ dst, int n4)
{
    int t = blockIdx.x * blockDim.x + threadIdx.x;
    if (t >= n4) return;
    float4 v = __ldg((const float4*)src + t);
    __half2 h0 = __floats2half2_rn(v.x, v.y);
    __half2 h1 = __floats2half2_rn(v.z, v.w);
    ((uint2*)dst)[t] = make_uint2(*(unsigned*)&h0, *(unsigned*)&h1);
}

__global__ void k_f2h3(const float* __restrict__ w1, const float* __restrict__ w2,
                       const float* __restrict__ w3, __half* __restrict__ dst)
{
    int t = blockIdx.x * blockDim.x + threadIdx.x;
    const int per = DD * DD / 4;
    if (t >= 3 * per) return;
    int m = t / per, i = t - m * per;
    const float* src = (m == 0) ? w1 : (m == 1) ? w2 : w3;
    float4 v = __ldg((const float4*)src + i);
    __half2 h0 = __floats2half2_rn(v.x, v.y);
    __half2 h1 = __floats2half2_rn(v.z, v.w);
    ((uint2*)dst)[t] = make_uint2(*(unsigned*)&h0, *(unsigned*)&h1);
}

// ---------------- histogram (ILP=4) ----------------
__global__ void k_hist4(const int* __restrict__ idx, int* __restrict__ hist, int E)
{
    int t = blockIdx.x * blockDim.x + threadIdx.x;
    int e0 = t * 4;
    if (e0 + 4 <= E) {
        int4 v = __ldg((const int4*)(idx + e0));
        atomicAdd(hist + v.x, 1);
        atomicAdd(hist + v.y, 1);
        atomicAdd(hist + v.z, 1);
        atomicAdd(hist + v.w, 1);
    } else {
        for (int e = e0; e < E; e++) atomicAdd(hist + __ldg(idx + e), 1);
    }
}

// ---------------- fused exclusive scan over 5 segments ----------------
struct Seg5 { int off[5]; int n[5]; };
__global__ void k_scan5(int* __restrict__ rowptr_base, int* __restrict__ cur_base, Seg5 segs)
{
    __shared__ int wsum[32];
    int off = segs.off[blockIdx.x];
    int N   = segs.n[blockIdx.x];
    int* hist = cur_base + off;
    int* rp   = rowptr_base + off;

    int tid = threadIdx.x;                 // blockDim = 1024
    int per = (N + 1023) >> 10;
    int lo = tid * per; if (lo > N) lo = N;
    int hi = lo + per;  if (hi > N) hi = N;

    int sum = 0;
    for (int i = lo; i < hi; i++) sum += hist[i];

    int lane = tid & 31, wid = tid >> 5;
    int v = sum;
#pragma unroll
    for (int o = 1; o < 32; o <<= 1) {
        int t = __shfl_up_sync(0xffffffffu, v, o);
        if (lane >= o) v += t;
    }
    if (lane == 31) wsum[wid] = v;
    __syncthreads();
    if (wid == 0) {
        int s = wsum[lane];
#pragma unroll
        for (int o = 1; o < 32; o <<= 1) {
            int t = __shfl_up_sync(0xffffffffu, s, o);
            if (lane >= o) s += t;
        }
        wsum[lane] = s;
    }
    __syncthreads();
    int excl = (v - sum) + (wid ? wsum[wid - 1] : 0);

    int run = excl;
    for (int i = lo; i < hi; i++) {
        int c = hist[i];
        rp[i] = run;
        hist[i] = run;
        run += c;
    }
    if (tid == 1023) rp[N] = excl + sum;
}

// ---------------- binning (ILP=4) ----------------
__global__ void k_bin_w4(const int*   __restrict__ sc_idx,
                         const int*   __restrict__ g_idx,
                         const float* __restrict__ ew,
                         int*  __restrict__ cursor,
                         int2* __restrict__ pgw,
                         int E)
{
    int t = blockIdx.x * blockDim.x + threadIdx.x;
    int e0 = t * 4;
    if (e0 + 4 <= E) {
        int4 b = __ldg((const int4*)(sc_idx + e0));
        int4 g = __ldg((const int4*)(g_idx + e0));
        float4 w = __ldg((const float4*)(ew + e0));
        int p0 = atomicAdd(cursor + b.x, 1);
        int p1 = atomicAdd(cursor + b.y, 1);
        int p2 = atomicAdd(cursor + b.z, 1);
        int p3 = atomicAdd(cursor + b.w, 1);
        pgw[p0] = make_int2(g.x, __float_as_int(w.x));
        pgw[p1] = make_int2(g.y, __float_as_int(w.y));
        pgw[p2] = make_int2(g.z, __float_as_int(w.z));
        pgw[p3] = make_int2(g.w, __float_as_int(w.w));
    } else {
        for (int e = e0; e < E; e++) {
            int b = __ldg(sc_idx + e);
            int p = atomicAdd(cursor + b, 1);
            pgw[p] = make_int2(__ldg(g_idx + e), __float_as_int(__ldg(ew + e)));
        }
    }
}

__global__ void k_bin_u4(const int* __restrict__ sc_idx,
                         const int* __restrict__ g_idx,
                         int* __restrict__ cursor,
                         int* __restrict__ pg,
                         int E)
{
    int t = blockIdx.x * blockDim.x + threadIdx.x;
    int e0 = t * 4;
    if (e0 + 4 <= E) {
        int4 b = __ldg((const int4*)(sc_idx + e0));
        int4 g = __ldg((const int4*)(g_idx + e0));
        int p0 = atomicAdd(cursor + b.x, 1);
        int p1 = atomicAdd(cursor + b.y, 1);
        int p2 = atomicAdd(cursor + b.z, 1);
        int p3 = atomicAdd(cursor + b.w, 1);
        pg[p0] = g.x;
        pg[p1] = g.y;
        pg[p2] = g.z;
        pg[p3] = g.w;
    } else {
        for (int e = e0; e < E; e++) {
            int b = __ldg(sc_idx + e);
            int p = atomicAdd(cursor + b, 1);
            pg[p] = __ldg(g_idx + e);
        }
    }
}

// ======== gather A: fp16 src, weighted(packed), out = half((mean + xb)*0.5) [MLP4] ========
__global__ void k_gather_msg_h16(const __half* __restrict__ feath,
                                 const int2*   __restrict__ pgw,
                                 const int*    __restrict__ rp,
                                 const float*  __restrict__ xb,
                                 __half* __restrict__ outh,
                                 int N)
{
    int t = blockIdx.x * blockDim.x + threadIdx.x;
    int n = t >> 5, lane = t & 31;
    if (n >= N) return;
    int start = __ldg(rp + n), end = __ldg(rp + n + 1);
    const uint2* fb = (const uint2*)feath;

    float4 acc = make_float4(0.f, 0.f, 0.f, 0.f);
    int j = start;
    for (; j + 4 <= end; j += 4) {
        int2 e0 = __ldg(pgw + j),     e1 = __ldg(pgw + j + 1);
        int2 e2 = __ldg(pgw + j + 2), e3 = __ldg(pgw + j + 3);
        uint2 u0 = __ldg(fb + (size_t)e0.x * 32 + lane);
        uint2 u1 = __ldg(fb + (size_t)e1.x * 32 + lane);
        uint2 u2 = __ldg(fb + (size_t)e2.x * 32 + lane);
        uint2 u3 = __ldg(fb + (size_t)e3.x * 32 + lane);
        float w0 = __int_as_float(e0.y), w1 = __int_as_float(e1.y);
        float w2 = __int_as_float(e2.y), w3 = __int_as_float(e3.y);
#pragma unroll
        for (int q = 0; q < 4; q++) {
            uint2 u = (q == 0) ? u0 : (q == 1) ? u1 : (q == 2) ? u2 : u3;
            float w = (q == 0) ? w0 : (q == 1) ? w1 : (q == 2) ? w2 : w3;
            float2 f0 = __half22float2(*(__half2*)&u.x);
            float2 f1 = __half22float2(*(__half2*)&u.y);
            acc.x += f0.x * w; acc.y += f0.y * w;
            acc.z += f1.x * w; acc.w += f1.y * w;
        }
    }
    for (; j < end; j++) {
        int2 e = __ldg(pgw + j);
        float w = __int_as_float(e.y);
        uint2 u = __ldg(fb + (size_t)e.x * 32 + lane);
        float2 f0 = __half22float2(*(__half2*)&u.x);
        float2 f1 = __half22float2(*(__half2*)&u.y);
        acc.x += f0.x * w; acc.y += f0.y * w; acc.z += f1.x * w; acc.w += f1.y * w;
    }
    int deg = end - start;
    float inv = 1.0f / (deg > 1 ? (float)deg : 1.0f);
    float4 x = __ldg((const float4*)(xb + (size_t)n * DD) + lane);
    float4 r;
    r.x = (acc.x * inv + x.x) * 0.5f;
    r.y = (acc.y * inv + x.y) * 0.5f;
    r.z = (acc.z * inv + x.z) * 0.5f;
    r.w = (acc.w * inv + x.w) * 0.5f;
    __half2 h0 = __floats2half2_rn(r.x, r.y);
    __half2 h1 = __floats2half2_rn(r.z, r.w);
    ((uint2*)outh)[(size_t)n * 32 + lane] = make_uint2(*(unsigned*)&h0, *(unsigned*)&h1);
}

// ======== gather B: fp16 src, unweighted, out = half(mean) [MLP4] ========
__global__ void k_gather_s_h(const __half* __restrict__ feath,
                             const int*    __restrict__ pg,
                             const int*    __restrict__ rp,
                             __half* __restrict__ outh,
                             int N)
{
    int t = blockIdx.x * blockDim.x + threadIdx.x;
    int n = t >> 5, lane = t & 31;
    if (n >= N) return;
    int start = __ldg(rp + n), end = __ldg(rp + n + 1);
    const uint2* fb = (const uint2*)feath;

    float4 acc = make_float4(0.f, 0.f, 0.f, 0.f);
    int j = start;
    for (; j + 4 <= end; j += 4) {
        int g0 = __ldg(pg + j), g1 = __ldg(pg + j + 1);
        int g2 = __ldg(pg + j + 2), g3 = __ldg(pg + j + 3);
        uint2 u0 = __ldg(fb + (size_t)g0 * 32 + lane);
        uint2 u1 = __ldg(fb + (size_t)g1 * 32 + lane);
        uint2 u2 = __ldg(fb + (size_t)g2 * 32 + lane);
        uint2 u3 = __ldg(fb + (size_t)g3 * 32 + lane);
#pragma unroll
        for (int q = 0; q < 4; q++) {
            uint2 u = (q == 0) ? u0 : (q == 1) ? u1 : (q == 2) ? u2 : u3;
            float2 f0 = __half22float2(*(__half2*)&u.x);
            float2 f1 = __half22float2(*(__half2*)&u.y);
            acc.x += f0.x; acc.y += f0.y; acc.z += f1.x; acc.w += f1.y;
        }
    }
    for (; j < end; j++) {
        int g = __ldg(pg + j);
        uint2 u = __ldg(fb + (size_t)g * 32 + lane);
        float2 f0 = __half22float2(*(__half2*)&u.x);
        float2 f1 = __half22float2(*(__half2*)&u.y);
        acc.x += f0.x; acc.y += f0.y; acc.z += f1.x; acc.w += f1.y;
    }
    int deg = end - start;
    float inv = 1.0f / (deg > 1 ? (float)deg : 1.0f);
    __half2 h0 = __floats2half2_rn(acc.x * inv, acc.y * inv);
    __half2 h1 = __floats2half2_rn(acc.z * inv, acc.w * inv);
    ((uint2*)outh)[(size_t)n * 32 + lane] = make_uint2(*(unsigned*)&h0, *(unsigned*)&h1);
}

// ======== gather C: fp16 src, unweighted, out = half((mean + xb)*0.5) [MLP4] ========
__global__ void k_gather_msg_hh(const __half* __restrict__ feath,
                                const int*    __restrict__ pg,
                                const int*    __restrict__ rp,
                                const float*  __restrict__ xb,
                                __half* __restrict__ outh,
                                int N)
{
    int t = blockIdx.x * blockDim.x + threadIdx.x;
    int n = t >> 5, lane = t & 31;
    if (n >= N) return;
    int start = __ldg(rp + n), end = __ldg(rp + n + 1);
    const uint2* fb = (const uint2*)feath;

    float4 acc = make_float4(0.f, 0.f, 0.f, 0.f);
    int j = start;
    for (; j + 4 <= end; j += 4) {
        int g0 = __ldg(pg + j), g1 = __ldg(pg + j + 1);
        int g2 = __ldg(pg + j + 2), g3 = __ldg(pg + j + 3);
        uint2 u0 = __ldg(fb + (size_t)g0 * 32 + lane);
        uint2 u1 = __ldg(fb + (size_t)g1 * 32 + lane);
        uint2 u2 = __ldg(fb + (size_t)g2 * 32 + lane);
        uint2 u3 = __ldg(fb + (size_t)g3 * 32 + lane);
#pragma unroll
        for (int q = 0; q < 4; q++) {
            uint2 u = (q == 0) ? u0 : (q == 1) ? u1 : (q == 2) ? u2 : u3;
            float2 f0 = __half22float2(*(__half2*)&u.x);
            float2 f1 = __half22float2(*(__half2*)&u.y);
            acc.x += f0.x; acc.y += f0.y; acc.z += f1.x; acc.w += f1.y;
        }
    }
    for (; j < end; j++) {
        int g = __ldg(pg + j);
        uint2 u = __ldg(fb + (size_t)g * 32 + lane);
        float2 f0 = __half22float2(*(__half2*)&u.x);
        float2 f1 = __half22float2(*(__half2*)&u.y);
        acc.x += f0.x; acc.y += f0.y; acc.z += f1.x; acc.w += f1.y;
    }
    int deg = end - start;
    float inv = 1.0f / (deg > 1 ? (float)deg : 1.0f);
    float4 x = __ldg((const float4*)(xb + (size_t)n * DD) + lane);
    float4 r;
    r.x = (acc.x * inv + x.x) * 0.5f;
    r.y = (acc.y * inv + x.y) * 0.5f;
    r.z = (acc.z * inv + x.z) * 0.5f;
    r.w = (acc.w * inv + x.w) * 0.5f;
    __half2 h0 = __floats2half2_rn(r.x, r.y);
    __half2 h1 = __floats2half2_rn(r.z, r.w);
    ((uint2*)outh)[(size_t)n * 32 + lane] = make_uint2(*(unsigned*)&h0, *(unsigned*)&h1);
}

// ======== dual gather: fp16 srcs, packed weight (b only), half outs [2-edge] ========
__global__ void k_gather_dual_h(const __half* __restrict__ feat_a,
                                const __half* __restrict__ feat_b,
                                const int2*   __restrict__ pgw,
                                const int*    __restrict__ rp,
                                __half* __restrict__ out_a,
                                __half* __restrict__ out_b,
                                int N)
{
    int t = blockIdx.x * blockDim.x + threadIdx.x;
    int n = t >> 5, lane = t & 31;
    if (n >= N) return;
    int start = __ldg(rp + n), end = __ldg(rp + n + 1);
    const uint2* fa = (const uint2*)feat_a;
    const uint2* fbp = (const uint2*)feat_b;

    float4 aa = make_float4(0.f, 0.f, 0.f, 0.f);
    float4 ab = make_float4(0.f, 0.f, 0.f, 0.f);
    int j = start;
    for (; j + 2 <= end; j += 2) {
        int2 e0 = __ldg(pgw + j), e1 = __ldg(pgw + j + 1);
        uint2 a0 = __ldg(fa  + (size_t)e0.x * 32 + lane);
        uint2 b0 = __ldg(fbp + (size_t)e0.x * 32 + lane);
        uint2 a1 = __ldg(fa  + (size_t)e1.x * 32 + lane);
        uint2 b1 = __ldg(fbp + (size_t)e1.x * 32 + lane);
        float w0 = __int_as_float(e0.y), w1 = __int_as_float(e1.y);
        {
            float2 f0 = __half22float2(*(__half2*)&a0.x);
            float2 f1 = __half22float2(*(__half2*)&a0.y);
            float2 g0 = __half22float2(*(__half2*)&a1.x);
            float2 g1 = __half22float2(*(__half2*)&a1.y);
            aa.x += f0.x + g0.x; aa.y += f0.y + g0.y;
            aa.z += f1.x + g1.x; aa.w += f1.y + g1.y;
        }
        {
            float2 f0 = __half22float2(*(__half2*)&b0.x);
            float2 f1 = __half22float2(*(__half2*)&b0.y);
            float2 g0 = __half22float2(*(__half2*)&b1.x);
            float2 g1 = __half22float2(*(__half2*)&b1.y);
            ab.x += f0.x * w0 + g0.x * w1; ab.y += f0.y * w0 + g0.y * w1;
            ab.z += f1.x * w0 + g1.x * w1; ab.w += f1.y * w0 + g1.y * w1;
        }
    }
    for (; j < end; j++) {
        int2 e = __ldg(pgw + j);
        float w = __int_as_float(e.y);
        uint2 a = __ldg(fa  + (size_t)e.x * 32 + lane);
        uint2 b = __ldg(fbp + (size_t)e.x * 32 + lane);
        float2 f0 = __half22float2(*(__half2*)&a.x);
        float2 f1 = __half22float2(*(__half2*)&a.y);
        aa.x += f0.x; aa.y += f0.y; aa.z += f1.x; aa.w += f1.y;
        float2 h0 = __half22float2(*(__half2*)&b.x);
        float2 h1 = __half22float2(*(__half2*)&b.y);
        ab.x += h0.x * w; ab.y += h0.y * w; ab.z += h1.x * w; ab.w += h1.y * w;
    }
    int deg = end - start;
    float inv = 1.0f / (deg > 1 ? (float)deg : 1.0f);
    __half2 ha0 = __floats2half2_rn(aa.x * inv, aa.y * inv);
    __half2 ha1 = __floats2half2_rn(aa.z * inv, aa.w * inv);
    __half2 hb0 = __floats2half2_rn(ab.x * inv, ab.y * inv);
    __half2 hb1 = __floats2half2_rn(ab.z * inv, ab.w * inv);
    ((uint2*)out_a)[(size_t)n * 32 + lane] = make_uint2(*(unsigned*)&ha0, *(unsigned*)&ha1);
    ((uint2*)out_b)[(size_t)n * 32 + lane] = make_uint2(*(unsigned*)&hb0, *(unsigned*)&hb1);
}

// ======== fused GEMM x3 + attention: out = softmax-combined relu(x_k @ W_k^T + b_k) ========
#define APITCH 136
#define YPITCH 136
// smem: As[128*136] + Bs[128*136] + ysm[3*128*136] (all half) + scores[384] + wts[384] (float)
#define GA_SMEM ((2 * 128 * APITCH + 3 * 128 * YPITCH) * 2 + 2 * 384 * 4)

__device__ __forceinline__ unsigned smem_u32p(const void* p) {
    return (unsigned)__cvta_generic_to_shared(p);
}

__global__ void __launch_bounds__(256, 1)
k_gemm_att(const __half* __restrict__ x1h, const __half* __restrict__ x2h,
           const __half* __restrict__ x3h,
           const __half* __restrict__ WhBase,
           const float* __restrict__ b1, const float* __restrict__ b2,
           const float* __restrict__ b3,
           const float* __restrict__ att,
           float* __restrict__ out, int N)
{
    extern __shared__ __half smh[];
    __half* As = smh;                        // [128][APITCH]
    __half* Bs = As + 128 * APITCH;          // [128][APITCH]
    __half* ysm = Bs + 128 * APITCH;         // [3][128][YPITCH]
    float* scores = (float*)(ysm + 3 * 128 * YPITCH);  // [3][128]
    float* wts = scores + 384;                          // [3][128]

    int tid = threadIdx.x;
    int lane = tid & 31, wid = tid >> 5;
    int row0 = blockIdx.x * 128;
    int wm = wid * 16;
    int qr = lane & 7, q = lane >> 3;
    int cbase = (lane & 3) * 2;
    int lrow = wm + (lane >> 2);

    const __half* xs[3] = { x1h, x2h, x3h };
    const float*  bs[3] = { b1, b2, b3 };

#pragma unroll
    for (int k = 0; k < 3; k++) {
        if (k) __syncthreads();   // protect As/Bs reuse
        const __half* xh = xs[k];
        const __half* Wh = WhBase + k * DD * DD;

        for (int i = tid; i < 128 * 16; i += 256) {
            int r = i >> 4, c = i & 15;
            uint4 v = *((const uint4*)(Wh + r * DD) + c);
            *(uint4*)(Bs + r * APITCH + c * 8) = v;
        }
        for (int i = tid; i < 128 * 16; i += 256) {
            int r = i >> 4, c = i & 15;
            int row = row0 + r;
            uint4 v = make_uint4(0u, 0u, 0u, 0u);
            if (row < N) v = *((const uint4*)(xh + (size_t)row * DD) + c);
            *(uint4*)(As + r * APITCH + c * 8) = v;
        }
        __syncthreads();

        float d[16][4];
#pragma unroll
        for (int t = 0; t < 16; t++) { d[t][0] = d[t][1] = d[t][2] = d[t][3] = 0.f; }

#pragma unroll
        for (int kk = 0; kk < 8; kk++) {
            int arow = wm + qr + (q & 1) * 8;
            int acol = kk * 16 + (q >> 1) * 8;
            unsigned a0, a1, a2, a3;
            {
                unsigned addr = smem_u32p(As + arow * APITCH + acol);
                asm volatile("ldmatrix.sync.aligned.m8n8.x4.shared.b16 {%0,%1,%2,%3}, [%4];"
                             : "=r"(a0), "=r"(a1), "=r"(a2), "=r"(a3) : "r"(addr));
            }
#pragma unroll
            for (int bt = 0; bt < 8; bt++) {
                int brow = bt * 16 + qr + (q >> 1) * 8;
                int bcol = kk * 16 + (q & 1) * 8;
                unsigned b0, b1r, b2r, b3r;
                unsigned addr = smem_u32p(Bs + brow * APITCH + bcol);
                asm volatile("ldmatrix.sync.aligned.m8n8.x4.shared.b16 {%0,%1,%2,%3}, [%4];"
                             : "=r"(b0), "=r"(b1r), "=r"(b2r), "=r"(b3r) : "r"(addr));
                float* dt0 = d[2 * bt];
                asm volatile("mma.sync.aligned.m16n8k16.row.col.f32.f16.f16.f32 "
                             "{%0,%1,%2,%3}, {%4,%5,%6,%7}, {%8,%9}, {%0,%1,%2,%3};"
                             : "+f"(dt0[0]), "+f"(dt0[1]), "+f"(dt0[2]), "+f"(dt0[3])
                             : "r"(a0), "r"(a1), "r"(a2), "r"(a3), "r"(b0), "r"(b1r));
                float* dt1 = d[2 * bt + 1];
                asm volatile("mma.sync.aligned.m16n8k16.row.col.f32.f16.f16.f32 "
                             "{%0,%1,%2,%3}, {%4,%5,%6,%7}, {%8,%9}, {%0,%1,%2,%3};"
                             : "+f"(dt1[0]), "+f"(dt1[1]), "+f"(dt1[2]), "+f"(dt1[3])
                             : "r"(a0), "r"(a1), "r"(a2), "r"(a3), "r"(b2r), "r"(b3r));
            }
        }

        // epilogue: bias + relu -> ysm (fp16); per-row attention score partials
        const float* bias = bs[k];
        const float* attk = att + k * DD;
        __half* yk = ysm + k * 128 * YPITCH;
        float sc_lo = 0.f, sc_hi = 0.f;
#pragma unroll
        for (int t = 0; t < 16; t++) {
            int col = t * 8 + cbase;
            float bb0 = __ldg(bias + col), bb1 = __ldg(bias + col + 1);
            float av0 = __ldg(attk + col), av1 = __ldg(attk + col + 1);
            float a0 = fmaxf(d[t][0] + bb0, 0.f), a1 = fmaxf(d[t][1] + bb1, 0.f);
            float a2 = fmaxf(d[t][2] + bb0, 0.f), a3 = fmaxf(d[t][3] + bb1, 0.f);
            sc_lo += a0 * av0 + a1 * av1;
            sc_hi += a2 * av0 + a3 * av1;
            __half2 hlo = __floats2half2_rn(a0, a1);
            __half2 hhi = __floats2half2_rn(a2, a3);
            *(__half2*)(yk + lrow * YPITCH + col) = hlo;
            *(__half2*)(yk + (lrow + 8) * YPITCH + col) = hhi;
        }
        sc_lo += __shfl_xor_sync(0xffffffffu, sc_lo, 1);
        sc_lo += __shfl_xor_sync(0xffffffffu, sc_lo, 2);
        sc_hi += __shfl_xor_sync(0xffffffffu, sc_hi, 1);
        sc_hi += __shfl_xor_sync(0xffffffffu, sc_hi, 2);
        if ((lane & 3) == 0) {
            scores[k * 128 + lrow] = sc_lo;
            scores[k * 128 + lrow + 8] = sc_hi;
        }
    }
    __syncthreads();

    // per-row softmax over 3 metapaths
    if (tid < 128) {
        float s1 = scores[tid], s2 = scores[128 + tid], s3 = scores[256 + tid];
        float m = fmaxf(s1, fmaxf(s2, s3));
        float e1 = __expf(s1 - m), e2 = __expf(s2 - m), e3 = __expf(s3 - m);
        float inv = 1.0f / (e1 + e2 + e3);
        wts[tid] = e1 * inv;
        wts[128 + tid] = e2 * inv;
        wts[256 + tid] = e3 * inv;
    }
    __syncthreads();

    // combine + write out
    for (int i = tid; i < 128 * 32; i += 256) {
        int row = i >> 5;
        int grow = row0 + row;
        if (grow >= N) continue;
        int c = (i & 31) * 4;
        float w1 = wts[row], w2 = wts[128 + row], w3 = wts[256 + row];
        uint2 u1 = *(uint2*)(ysm + 0 * 128 * YPITCH + row * YPITCH + c);
        uint2 u2 = *(uint2*)(ysm + 1 * 128 * YPITCH + row * YPITCH + c);
        uint2 u3 = *(uint2*)(ysm + 2 * 128 * YPITCH + row * YPITCH + c);
        float2 p10 = __half22float2(*(__half2*)&u1.x), p11 = __half22float2(*(__half2*)&u1.y);
        float2 p20 = __half22float2(*(__half2*)&u2.x), p21 = __half22float2(*(__half2*)&u2.y);
        float2 p30 = __half22float2(*(__half2*)&u3.x), p31 = __half22float2(*(__half2*)&u3.y);
        float4 o;
        o.x = w1 * p10.x + w2 * p20.x + w3 * p30.x;
        o.y = w1 * p10.y + w2 * p20.y + w3 * p30.y;
        o.z = w1 * p11.x + w2 * p21.x + w3 * p31.x;
        o.w = w1 * p11.y + w2 * p21.y + w3 * p31.y;
        *(float4*)(out + (size_t)grow * DD + c) = o;
    }
}

// ---------------- launch ----------------
static inline int cdiv(long long a, int b) { return (int)((a + b - 1) / b); }

extern "C" void kernel_launch(void* const* d_in, const int* in_sizes, int n_in,
                              void* d_out, int out_size)
{
    const float* x_node   = (const float*)d_in[0];
    const float* x1       = (const float*)d_in[1];
    const float* x2       = (const float*)d_in[2];
    const int*   ei1_src  = (const int*)d_in[3];
    const int*   ei1_dst  = (const int*)d_in[4];
    const int*   ei2_src  = (const int*)d_in[5];
    const int*   ei2_dst  = (const int*)d_in[6];
    const int*   ei12_src = (const int*)d_in[7];
    const int*   ei12_dst = (const int*)d_in[8];
    const float* ew1      = (const float*)d_in[9];
    const float* ew2      = (const float*)d_in[10];
    const float* W1       = (const float*)d_in[11];
    const float* b1       = (const float*)d_in[12];
    const float* W2       = (const float*)d_in[13];
    const float* b2       = (const float*)d_in[14];
    const float* W12      = (const float*)d_in[15];
    const float* b12      = (const float*)d_in[16];
    const float* att      = (const float*)d_in[17];
    float* out = (float*)d_out;

    int n0  = in_sizes[0] / DD;
    int n1  = in_sizes[1] / DD;
    int n2  = in_sizes[2] / DD;
    int e1  = in_sizes[3];
    int e2  = in_sizes[5];
    int e12 = in_sizes[7];

    __half *xnodeh, *net1h, *net2h, *net2bh, *s1h, *s2h, *s12h, *Wh;
    int *rowptr, *cursor, *pb1g, *pcg;
    int2 *p1gw, *p2gw, *pb2gw;
    cudaGetSymbolAddress((void**)&xnodeh, g_xnodeh);
    cudaGetSymbolAddress((void**)&net1h,  g_net1h);
    cudaGetSymbolAddress((void**)&net2h,  g_net2h);
    cudaGetSymbolAddress((void**)&net2bh, g_net2bh);
    cudaGetSymbolAddress((void**)&s1h,  g_s1h);
    cudaGetSymbolAddress((void**)&s2h,  g_s2h);
    cudaGetSymbolAddress((void**)&s12h, g_s12h);
    cudaGetSymbolAddress((void**)&Wh,   g_Wh);
    cudaGetSymbolAddress((void**)&rowptr, g_rowptr);
    cudaGetSymbolAddress((void**)&cursor, g_cursor);
    cudaGetSymbolAddress((void**)&p1gw,  g_p1gw);
    cudaGetSymbolAddress((void**)&p2gw,  g_p2gw);
    cudaGetSymbolAddress((void**)&pb2gw, g_pb2gw);
    cudaGetSymbolAddress((void**)&pb1g,  g_pb1g);
    cudaGetSymbolAddress((void**)&pcg,   g_pcg);

    cudaFuncSetAttribute(k_gemm_att, cudaFuncAttributeMaxDynamicSharedMemorySize, GA_SMEM);

    cudaMemsetAsync(cursor, 0, (size_t)RPTOT * sizeof(int), 0);

    const int BT = 256;
    #define E4GRID(E) cdiv(((long long)(E) + 3) / 4, BT)

    // --- conversions ---
    k_f2h<<<cdiv((long long)n0 * 32, BT), BT>>>(x_node, xnodeh, n0 * 32);
    k_f2h3<<<cdiv(3 * DD * DD / 4, BT), BT>>>(W1, W2, W12, Wh);

    // --- histograms ---
    k_hist4<<<E4GRID(e1), BT>>>(ei1_dst,   cursor + RP1,  e1);
    k_hist4<<<E4GRID(e2), BT>>>(ei2_dst,   cursor + RP2,  e2);
    k_hist4<<<E4GRID(e1), BT>>>(ei1_src,   cursor + RPB1, e1);
    k_hist4<<<E4GRID(e12), BT>>>(ei12_dst, cursor + RPC,  e12);
    k_hist4<<<E4GRID(e2), BT>>>(ei2_src,   cursor + RPB2, e2);

    // --- fused scans ---
    Seg5 segs;
    segs.off[0] = RP1;  segs.n[0] = n1;
    segs.off[1] = RP2;  segs.n[1] = n2;
    segs.off[2] = RPB1; segs.n[2] = n0;
    segs.off[3] = RPC;  segs.n[3] = n2;
    segs.off[4] = RPB2; segs.n[4] = n0;
    k_scan5<<<5, 1024>>>(rowptr, cursor, segs);

    // --- binning ---
    k_bin_w4<<<E4GRID(e1), BT>>>(ei1_dst,  ei1_src,  ew1, cursor + RP1,  p1gw,  e1);
    k_bin_w4<<<E4GRID(e2), BT>>>(ei2_dst,  ei2_src,  ew2, cursor + RP2,  p2gw,  e2);
    k_bin_u4<<<E4GRID(e1), BT>>>(ei1_src,  ei1_dst,  cursor + RPB1, pb1g, e1);
    k_bin_u4<<<E4GRID(e12), BT>>>(ei12_dst, ei12_src, cursor + RPC,  pcg,  e12);
    k_bin_w4<<<E4GRID(e2), BT>>>(ei2_src,  ei2_dst,  ew2, cursor + RPB2, pb2gw, e2);

    // --- gathers (frozen shapes) ---
    k_gather_msg_h16<<<cdiv((long long)n1 * 32, BT), BT>>>(xnodeh, p1gw, rowptr + RP1, x1, net1h, n1);
    k_gather_msg_h16<<<cdiv((long long)n2 * 32, BT), BT>>>(xnodeh, p2gw, rowptr + RP2, x2, net2h, n2);
    k_gather_s_h<<<cdiv((long long)n0 * 32, BT), BT>>>(net1h, pb1g, rowptr + RPB1, s1h, n0);
    k_gather_msg_hh<<<cdiv((long long)n2 * 32, BT), BT>>>(net1h, pcg, rowptr + RPC, x2, net2bh, n2);
    k_gather_dual_h<<<cdiv((long long)n0 * 32, BT), BT>>>(net2h, net2bh, pb2gw, rowptr + RPB2, s2h, s12h, n0);

    // --- fused GEMM x3 + attention ---
    k_gemm_att<<<cdiv(n0, 128), 256, GA_SMEM>>>(s1h, s2h, s12h, Wh, b1, b2, b12, att, out, n0);
}